// round 1
// baseline (speedup 1.0000x reference)
#include <cuda_runtime.h>
#include <cuda_bf16.h>
#include <math.h>

// ---------------- problem constants ----------------
#define S    2048
#define Hh   4096
#define NH   32
#define DN   128
#define DR   64
#define DV   128
#define QKD  192          // DN + DR
#define RQ   1536
#define RKV  512
#define CKVW 576          // RKV + DR

// ---------------- scratch (device globals; allocation-free) ----------------
__device__ float g_qa  [S * RQ];            // hidden @ q_a_w^T
__device__ float g_qan [S * RQ];            // rmsnorm(q_a)
__device__ float g_q   [S * NH * QKD];      // q_b output
__device__ float g_ckv [S * CKVW];          // hidden @ kv_a_w^T
__device__ float g_ckvn[S * RKV];           // rmsnorm(ckv[:, :512])
__device__ float g_kv  [S * NH * (DN+DV)];  // kv_b output
__device__ float g_Q   [(size_t)NH * S * QKD];
__device__ float g_K   [(size_t)NH * S * QKD];
__device__ float g_V   [(size_t)NH * S * DV];
__device__ float g_Sc  [(size_t)NH * S * S];    // scores / probs (512 MB)
__device__ float g_attn[S * Hh];            // attention out, [s, h*128+d]

// ---------------- generic NT GEMM: C[M,N] = A[M,K] * B[N,K]^T ----------------
// 128x128 tile, BK=16, 256 threads, 8x8 micro-tile per thread.
__global__ void gemm_nt(const float* __restrict__ A, const float* __restrict__ B,
                        float* __restrict__ C, int M, int N, int K) {
    __shared__ float As[16][129];
    __shared__ float Bs[16][129];
    const int tid = threadIdx.x;
    const int bm = blockIdx.y * 128, bn = blockIdx.x * 128;
    const int tx = tid & 15, ty = tid >> 4;
    const int lrow = tid >> 4, lcol = tid & 15;
    float acc[8][8];
#pragma unroll
    for (int i = 0; i < 8; i++)
#pragma unroll
        for (int j = 0; j < 8; j++) acc[i][j] = 0.f;

    for (int k0 = 0; k0 < K; k0 += 16) {
#pragma unroll
        for (int i = 0; i < 8; i++) {
            int r = lrow + i * 16;
            int gk = k0 + lcol;
            int gm = bm + r;
            As[lcol][r] = (gm < M) ? A[(size_t)gm * K + gk] : 0.f;
            int gn = bn + r;
            Bs[lcol][r] = (gn < N) ? B[(size_t)gn * K + gk] : 0.f;
        }
        __syncthreads();
#pragma unroll
        for (int kk = 0; kk < 16; kk++) {
            float a[8], b[8];
#pragma unroll
            for (int i = 0; i < 8; i++) a[i] = As[kk][ty + 16 * i];
#pragma unroll
            for (int j = 0; j < 8; j++) b[j] = Bs[kk][tx + 16 * j];
#pragma unroll
            for (int i = 0; i < 8; i++)
#pragma unroll
                for (int j = 0; j < 8; j++)
                    acc[i][j] = fmaf(a[i], b[j], acc[i][j]);
        }
        __syncthreads();
    }
#pragma unroll
    for (int i = 0; i < 8; i++) {
        int gm = bm + ty + 16 * i;
        if (gm >= M) continue;
#pragma unroll
        for (int j = 0; j < 8; j++) {
            int gn = bn + tx + 16 * j;
            if (gn < N) C[(size_t)gm * N + gn] = acc[i][j];
        }
    }
}

// ---------------- rmsnorm over first K cols of each row ----------------
__global__ void rmsnorm_kernel(const float* __restrict__ X, const float* __restrict__ w,
                               float* __restrict__ Y, int K, int ldx, int ldy) {
    const int row = blockIdx.x;
    const float* x = X + (size_t)row * ldx;
    float* y = Y + (size_t)row * ldy;
    float ss = 0.f;
    for (int j = threadIdx.x; j < K; j += blockDim.x) { float v = x[j]; ss += v * v; }
    __shared__ float red[256];
    red[threadIdx.x] = ss;
    __syncthreads();
    for (int s = 128; s > 0; s >>= 1) {
        if (threadIdx.x < s) red[threadIdx.x] += red[threadIdx.x + s];
        __syncthreads();
    }
    float inv = rsqrtf(red[0] / (float)K + 1e-6f);
    for (int j = threadIdx.x; j < K; j += blockDim.x) y[j] = x[j] * inv * w[j];
}

// ---------------- build Q[h][s][0..192) with RoPE on last 64 ----------------
__global__ void build_q(const float* __restrict__ q, const float* __restrict__ freqs,
                        float* __restrict__ Qb) {
    const int s = blockIdx.x, h = blockIdx.y, d = threadIdx.x; // 192 threads
    const float* qr = q + (size_t)s * (NH * QKD) + h * QKD;
    float val;
    if (d < DN) {
        val = qr[d];
    } else {
        int u = d - DN, t = u >> 1;
        float f = freqs[s * (DR / 2) + t];
        float c = cosf(f), sn = sinf(f);
        float xr = qr[DN + 2 * t], xi = qr[DN + 2 * t + 1];
        val = (u & 1) ? (xr * sn + xi * c) : (xr * c - xi * sn);
    }
    Qb[((size_t)h * S + s) * QKD + d] = val;
}

// ---------------- build K[h][s][0..192) and V[h][s][0..128) ----------------
__global__ void build_kv(const float* __restrict__ kv, const float* __restrict__ ckv,
                         const float* __restrict__ freqs,
                         float* __restrict__ Kb, float* __restrict__ Vb) {
    const int s = blockIdx.x, h = blockIdx.y, d = threadIdx.x; // 320 threads
    const float* kvr = kv + (size_t)s * (NH * (DN + DV)) + h * (DN + DV);
    if (d < DN) {
        Kb[((size_t)h * S + s) * QKD + d] = kvr[d];
    } else if (d < QKD) {
        int u = d - DN, t = u >> 1;
        float f = freqs[s * (DR / 2) + t];
        float c = cosf(f), sn = sinf(f);
        const float* kr = ckv + (size_t)s * CKVW + RKV;
        float xr = kr[2 * t], xi = kr[2 * t + 1];
        Kb[((size_t)h * S + s) * QKD + d] = (u & 1) ? (xr * sn + xi * c) : (xr * c - xi * sn);
    } else {
        int dv = d - QKD;
        Vb[((size_t)h * S + s) * DV + dv] = kvr[DN + dv];
    }
}

// ---------------- batched scores: Sc[h] = Q[h] * K[h]^T (causal tiles only) ------
__global__ void scores_gemm(const float* __restrict__ Qb, const float* __restrict__ Kb,
                            float* __restrict__ Sc) {
    if (blockIdx.x > blockIdx.y) return;  // tile strictly above diagonal: never read
    const int h = blockIdx.z;
    const float* A = Qb + (size_t)h * S * QKD;
    const float* B = Kb + (size_t)h * S * QKD;
    float* C = Sc + (size_t)h * S * S;
    __shared__ float As[16][129];
    __shared__ float Bs[16][129];
    const int tid = threadIdx.x;
    const int bm = blockIdx.y * 128, bn = blockIdx.x * 128;
    const int tx = tid & 15, ty = tid >> 4;
    const int lrow = tid >> 4, lcol = tid & 15;
    float acc[8][8];
#pragma unroll
    for (int i = 0; i < 8; i++)
#pragma unroll
        for (int j = 0; j < 8; j++) acc[i][j] = 0.f;

    for (int k0 = 0; k0 < QKD; k0 += 16) {
#pragma unroll
        for (int i = 0; i < 8; i++) {
            int r = lrow + i * 16;
            int gk = k0 + lcol;
            As[lcol][r] = A[(size_t)(bm + r) * QKD + gk];
            Bs[lcol][r] = B[(size_t)(bn + r) * QKD + gk];
        }
        __syncthreads();
#pragma unroll
        for (int kk = 0; kk < 16; kk++) {
            float a[8], b[8];
#pragma unroll
            for (int i = 0; i < 8; i++) a[i] = As[kk][ty + 16 * i];
#pragma unroll
            for (int j = 0; j < 8; j++) b[j] = Bs[kk][tx + 16 * j];
#pragma unroll
            for (int i = 0; i < 8; i++)
#pragma unroll
                for (int j = 0; j < 8; j++)
                    acc[i][j] = fmaf(a[i], b[j], acc[i][j]);
        }
        __syncthreads();
    }
#pragma unroll
    for (int i = 0; i < 8; i++)
#pragma unroll
        for (int j = 0; j < 8; j++)
            C[(size_t)(bm + ty + 16 * i) * S + (bn + tx + 16 * j)] = acc[i][j];
}

// ---------------- causal softmax, in place, scale applied here ----------------
__global__ void softmax_causal(float* __restrict__ Sc) {
    const int i = blockIdx.x, h = blockIdx.y;
    float* row = Sc + ((size_t)h * S + i) * S;
    const int n = i + 1;
    const float scale = 0.072168783648703220563f;  // 192^-0.5
    __shared__ float red[256];
    float m = -1e30f;
    for (int j = threadIdx.x; j < n; j += 256) m = fmaxf(m, row[j]);
    red[threadIdx.x] = m;
    __syncthreads();
    for (int s = 128; s > 0; s >>= 1) {
        if (threadIdx.x < s) red[threadIdx.x] = fmaxf(red[threadIdx.x], red[threadIdx.x + s]);
        __syncthreads();
    }
    float rmax = red[0];
    __syncthreads();
    float sum = 0.f;
    for (int j = threadIdx.x; j < n; j += 256) sum += expf((row[j] - rmax) * scale);
    red[threadIdx.x] = sum;
    __syncthreads();
    for (int s = 128; s > 0; s >>= 1) {
        if (threadIdx.x < s) red[threadIdx.x] += red[threadIdx.x + s];
        __syncthreads();
    }
    float inv = 1.f / red[0];
    for (int j = threadIdx.x; j < S; j += 256) {
        float v = (j < n) ? expf((row[j] - rmax) * scale) * inv : 0.f;
        row[j] = v;
    }
}

// ---------------- PV: attn[i, h*128+d] = sum_j P[h][i][j] V[h][j][d] ----------
__global__ void gemm_pv(const float* __restrict__ P, const float* __restrict__ Vb,
                        float* __restrict__ Out) {
    const int h = blockIdx.z;
    const float* A = P + (size_t)h * S * S;
    const float* B = Vb + (size_t)h * S * DV;
    const int bm = blockIdx.y * 128;
    const int Keff = bm + 128;     // causal: probs are zero for j > i
    __shared__ float As[16][129];
    __shared__ float Bs[16][129];
    const int tid = threadIdx.x;
    const int tx = tid & 15, ty = tid >> 4;
    const int lrow = tid >> 4, lcol = tid & 15;
    float acc[8][8];
#pragma unroll
    for (int i = 0; i < 8; i++)
#pragma unroll
        for (int j = 0; j < 8; j++) acc[i][j] = 0.f;

    for (int k0 = 0; k0 < Keff; k0 += 16) {
#pragma unroll
        for (int i = 0; i < 8; i++) {
            int r = lrow + i * 16;
            As[lcol][r] = A[(size_t)(bm + r) * S + (k0 + lcol)];
        }
        // B tile: 16 x 128, linear cooperative load
#pragma unroll
        for (int i = 0; i < 8; i++) {
            int lin = tid + i * 256;
            int kr = lin >> 7, dd = lin & 127;
            Bs[kr][dd] = B[(size_t)(k0 + kr) * DV + dd];
        }
        __syncthreads();
#pragma unroll
        for (int kk = 0; kk < 16; kk++) {
            float a[8], b[8];
#pragma unroll
            for (int i = 0; i < 8; i++) a[i] = As[kk][ty + 16 * i];
#pragma unroll
            for (int j = 0; j < 8; j++) b[j] = Bs[kk][tx + 16 * j];
#pragma unroll
            for (int i = 0; i < 8; i++)
#pragma unroll
                for (int j = 0; j < 8; j++)
                    acc[i][j] = fmaf(a[i], b[j], acc[i][j]);
        }
        __syncthreads();
    }
#pragma unroll
    for (int i = 0; i < 8; i++) {
        int gi = bm + ty + 16 * i;
#pragma unroll
        for (int j = 0; j < 8; j++) {
            int gd = tx + 16 * j;
            Out[(size_t)gi * Hh + h * DV + gd] = acc[i][j];
        }
    }
}

// ---------------- host ----------------
static float* sym_addr(const void* symbol) {
    void* p = nullptr;
    cudaGetSymbolAddress(&p, symbol);
    return (float*)p;
}

extern "C" void kernel_launch(void* const* d_in, const int* in_sizes, int n_in,
                              void* d_out, int out_size) {
    const float* hidden   = (const float*)d_in[0];  // [1,2048,4096]
    const float* freqs    = (const float*)d_in[1];  // [1,2048,32]
    const float* q_a_w    = (const float*)d_in[2];  // [1536,4096]
    const float* q_a_ln_w = (const float*)d_in[3];  // [1536]
    const float* q_b_w    = (const float*)d_in[4];  // [6144,1536]
    const float* kv_a_w   = (const float*)d_in[5];  // [576,4096]
    const float* kv_a_ln_w= (const float*)d_in[6];  // [512]
    const float* kv_b_w   = (const float*)d_in[7];  // [8192,512]
    const float* o_w      = (const float*)d_in[8];  // [4096,4096]
    float* out = (float*)d_out;

    float* qa   = sym_addr(g_qa);
    float* qan  = sym_addr(g_qan);
    float* q    = sym_addr(g_q);
    float* ckv  = sym_addr(g_ckv);
    float* ckvn = sym_addr(g_ckvn);
    float* kv   = sym_addr(g_kv);
    float* Qb   = sym_addr(g_Q);
    float* Kb   = sym_addr(g_K);
    float* Vb   = sym_addr(g_V);
    float* Sc   = sym_addr(g_Sc);
    float* attn = sym_addr(g_attn);

    dim3 blk(256);

    // 1) q_a = hidden @ q_a_w^T       [2048,1536]
    gemm_nt<<<dim3(RQ / 128, S / 128), blk>>>(hidden, q_a_w, qa, S, RQ, Hh);
    // 2) rmsnorm(q_a)
    rmsnorm_kernel<<<S, 256>>>(qa, q_a_ln_w, qan, RQ, RQ, RQ);
    // 3) q = qan @ q_b_w^T            [2048,6144]
    gemm_nt<<<dim3(NH * QKD / 128, S / 128), blk>>>(qan, q_b_w, q, S, NH * QKD, RQ);
    // 4) ckv = hidden @ kv_a_w^T      [2048,576]
    gemm_nt<<<dim3((CKVW + 127) / 128, S / 128), blk>>>(hidden, kv_a_w, ckv, S, CKVW, Hh);
    // 5) rmsnorm(ckv[:, :512])
    rmsnorm_kernel<<<S, 256>>>(ckv, kv_a_ln_w, ckvn, RKV, CKVW, RKV);
    // 6) kv = ckvn @ kv_b_w^T         [2048,8192]
    gemm_nt<<<dim3(NH * (DN + DV) / 128, S / 128), blk>>>(ckvn, kv_b_w, kv, S, NH * (DN + DV), RKV);
    // 7) assemble Q with RoPE
    build_q<<<dim3(S, NH), QKD>>>(q, freqs, Qb);
    // 8) assemble K (RoPE on shared rot part) and V
    build_kv<<<dim3(S, NH), QKD + DV>>>(kv, ckv, freqs, Kb, Vb);
    // 9) scores (causal tiles only)
    scores_gemm<<<dim3(S / 128, S / 128, NH), blk>>>(Qb, Kb, Sc);
    // 10) causal softmax in place
    softmax_causal<<<dim3(S, NH), 256>>>(Sc);
    // 11) attn = probs @ V, written as [s, h*128+d]
    gemm_pv<<<dim3(1, S / 128, NH), blk>>>(Sc, Vb, attn);
    // 12) out = attn @ o_w^T          [2048,4096]
    gemm_nt<<<dim3(Hh / 128, S / 128), blk>>>(attn, o_w, out, S, Hh, Hh);
}

// round 3
// speedup vs baseline: 1.8023x; 1.8023x over previous
#include <cuda_runtime.h>
#include <cuda_bf16.h>
#include <mma.h>
#include <math.h>
#include <cstdint>
#include <cstddef>
using namespace nvcuda;

// ---------------- problem constants ----------------
#define S    2048
#define Hh   4096
#define NH   32
#define DN   128
#define DR   64
#define DV   128
#define QKD  192          // DN + DR
#define RQ   1536
#define RKV  512
#define CKVW 576          // RKV + DR

#define BM 128
#define BN 128
#define BK 16
#define LDT 20            // padded leading dim for 16-wide k tiles (floats)
#define LDB_PV 132        // padded leading dim for 128-wide n tiles (floats)

// ---------------- scratch (device globals; allocation-free) ----------------
__device__ float g_qa  [S * RQ];
__device__ float g_qan [S * RQ];
__device__ float g_q   [S * NH * QKD];
__device__ float g_ckv [S * CKVW];
__device__ float g_ckvn[S * RKV];
__device__ float g_kv  [S * NH * (DN+DV)];
__device__ float g_Q   [(size_t)NH * S * QKD];
__device__ float g_K   [(size_t)NH * S * QKD];
__device__ float g_V   [(size_t)NH * S * DV];
__device__ float g_Sc  [(size_t)NH * S * S];
__device__ float g_attn[S * Hh];

// ---------------- cp.async helpers ----------------
__device__ __forceinline__ void cp_async16(void* smem, const void* gmem, bool pred) {
    unsigned int s = (unsigned int)__cvta_generic_to_shared(smem);
    int sz = pred ? 16 : 0;
    asm volatile("cp.async.cg.shared.global [%0], [%1], 16, %2;\n" :: "r"(s), "l"(gmem), "r"(sz));
}
__device__ __forceinline__ void cp_async_commit() { asm volatile("cp.async.commit_group;\n"); }
template<int N_> __device__ __forceinline__ void cp_async_wait() { asm volatile("cp.async.wait_group %0;\n" :: "n"(N_)); }

typedef wmma::fragment<wmma::matrix_a, 16,16,8, wmma::precision::tf32, wmma::row_major> FragA;
typedef wmma::fragment<wmma::matrix_b, 16,16,8, wmma::precision::tf32, wmma::col_major> FragBc;
typedef wmma::fragment<wmma::matrix_b, 16,16,8, wmma::precision::tf32, wmma::row_major> FragBr;
typedef wmma::fragment<wmma::accumulator, 16,16,8, float> FragC;

#define CVT_FRAG(f) { _Pragma("unroll") for (int _e = 0; _e < (f).num_elements; _e++) (f).x[_e] = wmma::__float_to_tf32((f).x[_e]); }

// ============ generic NT GEMM: C[M,N] = A[M,K] * B[N,K]^T (tf32) ============
// 128x128 block tile, BK=16, 256 threads, 8 warps in 2(M)x4(N), warp tile 64x32.
__global__ void gemm_nt_tc(const float* __restrict__ A, const float* __restrict__ B,
                           float* __restrict__ C, int M, int N, int K) {
    __shared__ alignas(16) float As[2][BM * LDT];
    __shared__ alignas(16) float Bs[2][BN * LDT];
    const int tid = threadIdx.x;
    const int warp = tid >> 5;
    const int wm = warp & 1, wn = warp >> 1;
    const int bm = blockIdx.y * BM, bn = blockIdx.x * BN;

    FragC c[4][2];
#pragma unroll
    for (int i = 0; i < 4; i++)
#pragma unroll
        for (int j = 0; j < 2; j++) wmma::fill_fragment(c[i][j], 0.f);

    const int T = K / BK;
    auto load_tiles = [&](int kt, int buf) {
        const int k0 = kt * BK;
#pragma unroll
        for (int u = 0; u < 2; u++) {
            int f = tid + u * 256;
            int row = f >> 2, col = (f & 3) * 4;
            cp_async16(&As[buf][row * LDT + col], A + (size_t)(bm + row) * K + k0 + col, true);
        }
#pragma unroll
        for (int u = 0; u < 2; u++) {
            int f = tid + u * 256;
            int row = f >> 2, col = (f & 3) * 4;
            bool p = (bn + row) < N;
            cp_async16(&Bs[buf][row * LDT + col],
                       B + (size_t)(p ? (bn + row) : 0) * K + k0 + col, p);
        }
        cp_async_commit();
    };

    load_tiles(0, 0);
    for (int t = 0; t < T; t++) {
        const int buf = t & 1;
        if (t + 1 < T) { load_tiles(t + 1, buf ^ 1); cp_async_wait<1>(); }
        else           { cp_async_wait<0>(); }
        __syncthreads();
#pragma unroll
        for (int kk = 0; kk < BK; kk += 8) {
            FragA a[4]; FragBc b[2];
#pragma unroll
            for (int i = 0; i < 4; i++) {
                wmma::load_matrix_sync(a[i], &As[buf][(wm * 64 + i * 16) * LDT + kk], LDT);
                CVT_FRAG(a[i]);
            }
#pragma unroll
            for (int j = 0; j < 2; j++) {
                wmma::load_matrix_sync(b[j], &Bs[buf][(wn * 32 + j * 16) * LDT + kk], LDT);
                CVT_FRAG(b[j]);
            }
#pragma unroll
            for (int i = 0; i < 4; i++)
#pragma unroll
                for (int j = 0; j < 2; j++)
                    wmma::mma_sync(c[i][j], a[i], b[j], c[i][j]);
        }
        __syncthreads();
    }
#pragma unroll
    for (int i = 0; i < 4; i++)
#pragma unroll
        for (int j = 0; j < 2; j++) {
            int gm = bm + wm * 64 + i * 16;
            int gn = bn + wn * 32 + j * 16;
            if (gn + 16 <= N)
                wmma::store_matrix_sync(&C[(size_t)gm * N + gn], c[i][j], N, wmma::mem_row_major);
        }
}

// ============ batched scores: Sc[h] = Q[h] * K[h]^T (causal tiles only) ============
__global__ void scores_tc(const float* __restrict__ Qb, const float* __restrict__ Kb,
                          float* __restrict__ Sc) {
    if (blockIdx.x > blockIdx.y) return;
    const int h = blockIdx.z;
    const float* A = Qb + (size_t)h * S * QKD;
    const float* B = Kb + (size_t)h * S * QKD;
    float* C = Sc + (size_t)h * S * S;
    __shared__ alignas(16) float As[2][BM * LDT];
    __shared__ alignas(16) float Bs[2][BN * LDT];
    const int tid = threadIdx.x;
    const int warp = tid >> 5;
    const int wm = warp & 1, wn = warp >> 1;
    const int bm = blockIdx.y * BM, bn = blockIdx.x * BN;

    FragC c[4][2];
#pragma unroll
    for (int i = 0; i < 4; i++)
#pragma unroll
        for (int j = 0; j < 2; j++) wmma::fill_fragment(c[i][j], 0.f);

    const int T = QKD / BK;  // 12
    auto load_tiles = [&](int kt, int buf) {
        const int k0 = kt * BK;
#pragma unroll
        for (int u = 0; u < 2; u++) {
            int f = tid + u * 256;
            int row = f >> 2, col = (f & 3) * 4;
            cp_async16(&As[buf][row * LDT + col], A + (size_t)(bm + row) * QKD + k0 + col, true);
            cp_async16(&Bs[buf][row * LDT + col], B + (size_t)(bn + row) * QKD + k0 + col, true);
        }
        cp_async_commit();
    };

    load_tiles(0, 0);
    for (int t = 0; t < T; t++) {
        const int buf = t & 1;
        if (t + 1 < T) { load_tiles(t + 1, buf ^ 1); cp_async_wait<1>(); }
        else           { cp_async_wait<0>(); }
        __syncthreads();
#pragma unroll
        for (int kk = 0; kk < BK; kk += 8) {
            FragA a[4]; FragBc b[2];
#pragma unroll
            for (int i = 0; i < 4; i++) {
                wmma::load_matrix_sync(a[i], &As[buf][(wm * 64 + i * 16) * LDT + kk], LDT);
                CVT_FRAG(a[i]);
            }
#pragma unroll
            for (int j = 0; j < 2; j++) {
                wmma::load_matrix_sync(b[j], &Bs[buf][(wn * 32 + j * 16) * LDT + kk], LDT);
                CVT_FRAG(b[j]);
            }
#pragma unroll
            for (int i = 0; i < 4; i++)
#pragma unroll
                for (int j = 0; j < 2; j++)
                    wmma::mma_sync(c[i][j], a[i], b[j], c[i][j]);
        }
        __syncthreads();
    }
#pragma unroll
    for (int i = 0; i < 4; i++)
#pragma unroll
        for (int j = 0; j < 2; j++) {
            int gm = bm + wm * 64 + i * 16;
            int gn = bn + wn * 32 + j * 16;
            wmma::store_matrix_sync(&C[(size_t)gm * S + gn], c[i][j], S, wmma::mem_row_major);
        }
}

// ============ batched PV (NN): attn[i, h*128+d] = sum_j P[h][i][j] V[h][j][d] ============
__global__ void pv_tc(const float* __restrict__ P, const float* __restrict__ Vb,
                      float* __restrict__ Out) {
    const int h = blockIdx.z;
    const float* A = P + (size_t)h * S * S;
    const float* B = Vb + (size_t)h * S * DV;
    const int bm = blockIdx.y * BM;
    const int Keff = bm + BM;  // causal: probs zero beyond the diagonal tile
    __shared__ alignas(16) float As[2][BM * LDT];
    __shared__ alignas(16) float Bs[2][BK * LDB_PV];
    const int tid = threadIdx.x;
    const int warp = tid >> 5;
    const int wm = warp & 1, wn = warp >> 1;

    FragC c[4][2];
#pragma unroll
    for (int i = 0; i < 4; i++)
#pragma unroll
        for (int j = 0; j < 2; j++) wmma::fill_fragment(c[i][j], 0.f);

    const int T = Keff / BK;
    auto load_tiles = [&](int kt, int buf) {
        const int k0 = kt * BK;
#pragma unroll
        for (int u = 0; u < 2; u++) {
            int f = tid + u * 256;
            int row = f >> 2, col = (f & 3) * 4;
            cp_async16(&As[buf][row * LDT + col], A + (size_t)(bm + row) * S + k0 + col, true);
        }
        // B tile: 16 k-rows x 128 n-cols, row-major
#pragma unroll
        for (int u = 0; u < 2; u++) {
            int f = tid + u * 256;
            int row = f >> 5, col = (f & 31) * 4;
            cp_async16(&Bs[buf][row * LDB_PV + col], B + (size_t)(k0 + row) * DV + col, true);
        }
        cp_async_commit();
    };

    load_tiles(0, 0);
    for (int t = 0; t < T; t++) {
        const int buf = t & 1;
        if (t + 1 < T) { load_tiles(t + 1, buf ^ 1); cp_async_wait<1>(); }
        else           { cp_async_wait<0>(); }
        __syncthreads();
#pragma unroll
        for (int kk = 0; kk < BK; kk += 8) {
            FragA a[4]; FragBr b[2];
#pragma unroll
            for (int i = 0; i < 4; i++) {
                wmma::load_matrix_sync(a[i], &As[buf][(wm * 64 + i * 16) * LDT + kk], LDT);
                CVT_FRAG(a[i]);
            }
#pragma unroll
            for (int j = 0; j < 2; j++) {
                wmma::load_matrix_sync(b[j], &Bs[buf][kk * LDB_PV + wn * 32 + j * 16], LDB_PV);
                CVT_FRAG(b[j]);
            }
#pragma unroll
            for (int i = 0; i < 4; i++)
#pragma unroll
                for (int j = 0; j < 2; j++)
                    wmma::mma_sync(c[i][j], a[i], b[j], c[i][j]);
        }
        __syncthreads();
    }
#pragma unroll
    for (int i = 0; i < 4; i++)
#pragma unroll
        for (int j = 0; j < 2; j++) {
            int gm = bm + wm * 64 + i * 16;
            int gn = wn * 32 + j * 16;
            wmma::store_matrix_sync(&Out[(size_t)gm * Hh + h * DV + gn], c[i][j], Hh, wmma::mem_row_major);
        }
}

// ---------------- rmsnorm over first K cols of each row ----------------
__global__ void rmsnorm_kernel(const float* __restrict__ X, const float* __restrict__ w,
                               float* __restrict__ Y, int K, int ldx, int ldy) {
    const int row = blockIdx.x;
    const float* x = X + (size_t)row * ldx;
    float* y = Y + (size_t)row * ldy;
    float ss = 0.f;
    for (int j = threadIdx.x; j < K; j += blockDim.x) { float v = x[j]; ss += v * v; }
    __shared__ float red[256];
    red[threadIdx.x] = ss;
    __syncthreads();
    for (int s = 128; s > 0; s >>= 1) {
        if (threadIdx.x < s) red[threadIdx.x] += red[threadIdx.x + s];
        __syncthreads();
    }
    float inv = rsqrtf(red[0] / (float)K + 1e-6f);
    for (int j = threadIdx.x; j < K; j += blockDim.x) y[j] = x[j] * inv * w[j];
}

// ---------------- build Q[h][s][0..192) with RoPE on last 64 ----------------
__global__ void build_q(const float* __restrict__ q, const float* __restrict__ freqs,
                        float* __restrict__ Qb) {
    const int s = blockIdx.x, h = blockIdx.y, d = threadIdx.x;
    const float* qr = q + (size_t)s * (NH * QKD) + h * QKD;
    float val;
    if (d < DN) {
        val = qr[d];
    } else {
        int u = d - DN, t = u >> 1;
        float f = freqs[s * (DR / 2) + t];
        float c = cosf(f), sn = sinf(f);
        float xr = qr[DN + 2 * t], xi = qr[DN + 2 * t + 1];
        val = (u & 1) ? (xr * sn + xi * c) : (xr * c - xi * sn);
    }
    Qb[((size_t)h * S + s) * QKD + d] = val;
}

// ---------------- build K[h][s][0..192) and V[h][s][0..128) ----------------
__global__ void build_kv(const float* __restrict__ kv, const float* __restrict__ ckv,
                         const float* __restrict__ freqs,
                         float* __restrict__ Kb, float* __restrict__ Vb) {
    const int s = blockIdx.x, h = blockIdx.y, d = threadIdx.x;
    const float* kvr = kv + (size_t)s * (NH * (DN + DV)) + h * (DN + DV);
    if (d < DN) {
        Kb[((size_t)h * S + s) * QKD + d] = kvr[d];
    } else if (d < QKD) {
        int u = d - DN, t = u >> 1;
        float f = freqs[s * (DR / 2) + t];
        float c = cosf(f), sn = sinf(f);
        const float* kr = ckv + (size_t)s * CKVW + RKV;
        float xr = kr[2 * t], xi = kr[2 * t + 1];
        Kb[((size_t)h * S + s) * QKD + d] = (u & 1) ? (xr * sn + xi * c) : (xr * c - xi * sn);
    } else {
        int dv = d - QKD;
        Vb[((size_t)h * S + s) * DV + dv] = kvr[DN + dv];
    }
}

// ---------------- causal softmax, in place ----------------
__global__ void softmax_causal(float* __restrict__ Sc) {
    const int i = blockIdx.x, h = blockIdx.y;
    float* row = Sc + ((size_t)h * S + i) * S;
    const int n = i + 1;
    const int n_pad = ((i >> 7) + 1) << 7;   // zero out to causal tile boundary only
    const float scale = 0.072168783648703220563f;  // 192^-0.5
    __shared__ float red[256];
    float m = -1e30f;
    for (int j = threadIdx.x; j < n; j += 256) m = fmaxf(m, row[j]);
    red[threadIdx.x] = m;
    __syncthreads();
    for (int s = 128; s > 0; s >>= 1) {
        if (threadIdx.x < s) red[threadIdx.x] = fmaxf(red[threadIdx.x], red[threadIdx.x + s]);
        __syncthreads();
    }
    float rmax = red[0];
    __syncthreads();
    float sum = 0.f;
    for (int j = threadIdx.x; j < n; j += 256) sum += expf((row[j] - rmax) * scale);
    red[threadIdx.x] = sum;
    __syncthreads();
    for (int s = 128; s > 0; s >>= 1) {
        if (threadIdx.x < s) red[threadIdx.x] += red[threadIdx.x + s];
        __syncthreads();
    }
    float inv = 1.f / red[0];
    for (int j = threadIdx.x; j < n_pad; j += 256) {
        float v = (j < n) ? expf((row[j] - rmax) * scale) * inv : 0.f;
        row[j] = v;
    }
}

// ---------------- host ----------------
static float* sym_addr(const void* symbol) {
    void* p = nullptr;
    cudaGetSymbolAddress(&p, symbol);
    return (float*)p;
}

extern "C" void kernel_launch(void* const* d_in, const int* in_sizes, int n_in,
                              void* d_out, int out_size) {
    const float* hidden    = (const float*)d_in[0];
    const float* freqs     = (const float*)d_in[1];
    const float* q_a_w     = (const float*)d_in[2];
    const float* q_a_ln_w  = (const float*)d_in[3];
    const float* q_b_w     = (const float*)d_in[4];
    const float* kv_a_w    = (const float*)d_in[5];
    const float* kv_a_ln_w = (const float*)d_in[6];
    const float* kv_b_w    = (const float*)d_in[7];
    const float* o_w       = (const float*)d_in[8];
    float* out = (float*)d_out;

    float* qa   = sym_addr(g_qa);
    float* qan  = sym_addr(g_qan);
    float* q    = sym_addr(g_q);
    float* ckv  = sym_addr(g_ckv);
    float* ckvn = sym_addr(g_ckvn);
    float* kv   = sym_addr(g_kv);
    float* Qb   = sym_addr(g_Q);
    float* Kb   = sym_addr(g_K);
    float* Vb   = sym_addr(g_V);
    float* Sc   = sym_addr(g_Sc);
    float* attn = sym_addr(g_attn);

    dim3 blk(256);

    // 1) q_a = hidden @ q_a_w^T       [2048,1536]
    gemm_nt_tc<<<dim3(RQ / 128, S / 128), blk>>>(hidden, q_a_w, qa, S, RQ, Hh);
    // 2) rmsnorm(q_a)
    rmsnorm_kernel<<<S, 256>>>(qa, q_a_ln_w, qan, RQ, RQ, RQ);
    // 3) q = qan @ q_b_w^T            [2048,6144]
    gemm_nt_tc<<<dim3(NH * QKD / 128, S / 128), blk>>>(qan, q_b_w, q, S, NH * QKD, RQ);
    // 4) ckv = hidden @ kv_a_w^T      [2048,576]
    gemm_nt_tc<<<dim3((CKVW + 127) / 128, S / 128), blk>>>(hidden, kv_a_w, ckv, S, CKVW, Hh);
    // 5) rmsnorm(ckv[:, :512])
    rmsnorm_kernel<<<S, 256>>>(ckv, kv_a_ln_w, ckvn, RKV, CKVW, RKV);
    // 6) kv = ckvn @ kv_b_w^T         [2048,8192]
    gemm_nt_tc<<<dim3(NH * (DN + DV) / 128, S / 128), blk>>>(ckvn, kv_b_w, kv, S, NH * (DN + DV), RKV);
    // 7) assemble Q with RoPE
    build_q<<<dim3(S, NH), QKD>>>(q, freqs, Qb);
    // 8) assemble K (RoPE) and V
    build_kv<<<dim3(S, NH), QKD + DV>>>(kv, ckv, freqs, Kb, Vb);
    // 9) scores (causal tiles only)
    scores_tc<<<dim3(S / 128, S / 128, NH), blk>>>(Qb, Kb, Sc);
    // 10) causal softmax in place
    softmax_causal<<<dim3(S, NH), 256>>>(Sc);
    // 11) attn = probs @ V
    pv_tc<<<dim3(1, S / 128, NH), blk>>>(Sc, Vb, attn);
    // 12) out = attn @ o_w^T          [2048,4096]
    gemm_nt_tc<<<dim3(Hh / 128, S / 128), blk>>>(attn, o_w, out, S, Hh, Hh);
}

// round 5
// speedup vs baseline: 2.0515x; 1.1383x over previous
#include <cuda_runtime.h>
#include <cuda_bf16.h>
#include <mma.h>
#include <math.h>
#include <cstdint>
#include <cstddef>
using namespace nvcuda;

// ---------------- problem constants ----------------
#define S    2048
#define Hh   4096
#define NH   32
#define DN   128
#define DR   64
#define DV   128
#define QKD  192          // DN + DR
#define RQ   1536
#define RKV  512
#define CKVW 576          // RKV + DR

#define BM 128
#define BN 128
#define BK 16
#define LDT 20

#define SM_SCALE 0.072168783648703220563f   // 192^-0.5

// ---------------- scratch (device globals; allocation-free) ----------------
__device__ float g_qa  [S * RQ];
__device__ float g_qan [S * RQ];
__device__ float g_q   [S * NH * QKD];
__device__ float g_ckv [S * CKVW];
__device__ float g_ckvn[S * RKV];
__device__ float g_kv  [S * NH * (DN+DV)];
__device__ float g_Q   [(size_t)NH * S * QKD];
__device__ float g_K   [(size_t)NH * S * QKD];
__device__ float g_V   [(size_t)NH * S * DV];
__device__ float g_attn[S * Hh];

// ---------------- cp.async helpers ----------------
__device__ __forceinline__ void cp_async16(void* smem, const void* gmem, bool pred) {
    unsigned int s = (unsigned int)__cvta_generic_to_shared(smem);
    int sz = pred ? 16 : 0;
    asm volatile("cp.async.cg.shared.global [%0], [%1], 16, %2;\n" :: "r"(s), "l"(gmem), "r"(sz));
}
__device__ __forceinline__ void cp_async_commit() { asm volatile("cp.async.commit_group;\n"); }
template<int N_> __device__ __forceinline__ void cp_async_wait() { asm volatile("cp.async.wait_group %0;\n" :: "n"(N_)); }

// ---------------- tf32 mma helpers ----------------
__device__ __forceinline__ uint32_t f2tf(float x) {
    uint32_t r; asm("cvt.rna.tf32.f32 %0, %1;" : "=r"(r) : "f"(x)); return r;
}
__device__ __forceinline__ void mma_tf32(float* c, const uint32_t* a, uint32_t b0, uint32_t b1) {
    asm("mma.sync.aligned.m16n8k8.row.col.f32.tf32.tf32.f32 "
        "{%0,%1,%2,%3},{%4,%5,%6,%7},{%8,%9},{%0,%1,%2,%3};"
        : "+f"(c[0]), "+f"(c[1]), "+f"(c[2]), "+f"(c[3])
        : "r"(a[0]), "r"(a[1]), "r"(a[2]), "r"(a[3]), "r"(b0), "r"(b1));
}

typedef wmma::fragment<wmma::matrix_a, 16,16,8, wmma::precision::tf32, wmma::row_major> FragA;
typedef wmma::fragment<wmma::matrix_b, 16,16,8, wmma::precision::tf32, wmma::col_major> FragBc;
typedef wmma::fragment<wmma::accumulator, 16,16,8, float> FragC;

#define CVT_FRAG(f) { _Pragma("unroll") for (int _e = 0; _e < (f).num_elements; _e++) (f).x[_e] = wmma::__float_to_tf32((f).x[_e]); }

// ============ generic NT GEMM: C[M,N] = A[M,K] * B[N,K]^T (tf32) ============
__global__ void gemm_nt_tc(const float* __restrict__ A, const float* __restrict__ B,
                           float* __restrict__ C, int M, int N, int K) {
    __shared__ alignas(16) float As[2][BM * LDT];
    __shared__ alignas(16) float Bs[2][BN * LDT];
    const int tid = threadIdx.x;
    const int warp = tid >> 5;
    const int wm = warp & 1, wn = warp >> 1;
    const int bm = blockIdx.y * BM, bn = blockIdx.x * BN;

    FragC c[4][2];
#pragma unroll
    for (int i = 0; i < 4; i++)
#pragma unroll
        for (int j = 0; j < 2; j++) wmma::fill_fragment(c[i][j], 0.f);

    const int T = K / BK;
    auto load_tiles = [&](int kt, int buf) {
        const int k0 = kt * BK;
#pragma unroll
        for (int u = 0; u < 2; u++) {
            int f = tid + u * 256;
            int row = f >> 2, col = (f & 3) * 4;
            cp_async16(&As[buf][row * LDT + col], A + (size_t)(bm + row) * K + k0 + col, true);
        }
#pragma unroll
        for (int u = 0; u < 2; u++) {
            int f = tid + u * 256;
            int row = f >> 2, col = (f & 3) * 4;
            bool p = (bn + row) < N;
            cp_async16(&Bs[buf][row * LDT + col],
                       B + (size_t)(p ? (bn + row) : 0) * K + k0 + col, p);
        }
        cp_async_commit();
    };

    load_tiles(0, 0);
    for (int t = 0; t < T; t++) {
        const int buf = t & 1;
        if (t + 1 < T) { load_tiles(t + 1, buf ^ 1); cp_async_wait<1>(); }
        else           { cp_async_wait<0>(); }
        __syncthreads();
#pragma unroll
        for (int kk = 0; kk < BK; kk += 8) {
            FragA a[4]; FragBc b[2];
#pragma unroll
            for (int i = 0; i < 4; i++) {
                wmma::load_matrix_sync(a[i], &As[buf][(wm * 64 + i * 16) * LDT + kk], LDT);
                CVT_FRAG(a[i]);
            }
#pragma unroll
            for (int j = 0; j < 2; j++) {
                wmma::load_matrix_sync(b[j], &Bs[buf][(wn * 32 + j * 16) * LDT + kk], LDT);
                CVT_FRAG(b[j]);
            }
#pragma unroll
            for (int i = 0; i < 4; i++)
#pragma unroll
                for (int j = 0; j < 2; j++)
                    wmma::mma_sync(c[i][j], a[i], b[j], c[i][j]);
        }
        __syncthreads();
    }
#pragma unroll
    for (int i = 0; i < 4; i++)
#pragma unroll
        for (int j = 0; j < 2; j++) {
            int gm = bm + wm * 64 + i * 16;
            int gn = bn + wn * 32 + j * 16;
            if (gn + 16 <= N)
                wmma::store_matrix_sync(&C[(size_t)gm * N + gn], c[i][j], N, wmma::mem_row_major);
        }
}

// ================== fused flash attention (tf32 mma.sync) ==================
// Block: 128 q rows of one head. 8 warps x 16 rows. 64-key tiles, online softmax.
#define KS_LD 196
#define VS_LD 136
#define PS_LD 68
#define KS_SZ (64 * KS_LD)
#define VS_SZ (64 * VS_LD)
#define PS_SZ (16 * PS_LD)
#define FLASH_SMEM ((2 * KS_SZ + 2 * VS_SZ + 8 * PS_SZ) * 4)

__global__ __launch_bounds__(256, 1)
void flash_attn(const float* __restrict__ Qb, const float* __restrict__ Kb,
                const float* __restrict__ Vb, float* __restrict__ Out) {
    extern __shared__ float sm[];
    float* KsB = sm;
    float* VsB = sm + 2 * KS_SZ;
    float* PsB = sm + 2 * KS_SZ + 2 * VS_SZ;

    const int qt   = (int)(gridDim.x - 1 - blockIdx.x);  // heavy tiles first
    const int h    = blockIdx.y;
    const int bm   = qt * 128;
    const int tid  = threadIdx.x;
    const int warp = tid >> 5, lane = tid & 31;
    const int g    = lane >> 2, t = lane & 3;
    const int row0 = bm + warp * 16 + g;
    const int row1 = row0 + 8;

    const float* Qh = Qb + (size_t)h * S * QKD;
    const float* Kh = Kb + (size_t)h * S * QKD;
    const float* Vh = Vb + (size_t)h * S * DV;
    float* Pw = PsB + warp * PS_SZ;

    // ---- preload Q fragments in tf32 (24 kgroups x 4 regs) ----
    uint32_t qa[24][4];
    {
        const float* q0 = Qh + (size_t)row0 * QKD;
        const float* q1 = Qh + (size_t)row1 * QKD;
#pragma unroll
        for (int kg = 0; kg < 24; kg++) {
            qa[kg][0] = f2tf(__ldg(q0 + 8 * kg + t));
            qa[kg][1] = f2tf(__ldg(q1 + 8 * kg + t));
            qa[kg][2] = f2tf(__ldg(q0 + 8 * kg + t + 4));
            qa[kg][3] = f2tf(__ldg(q1 + 8 * kg + t + 4));
        }
    }

    float o[16][4];
#pragma unroll
    for (int i = 0; i < 16; i++) { o[i][0] = o[i][1] = o[i][2] = o[i][3] = 0.f; }
    float m0 = -1e30f, m1 = -1e30f, l0 = 0.f, l1 = 0.f;

    const int NT = 2 * qt + 2;

    auto load_kv = [&](int jtile, int buf) {
        const float* ksrc = Kh + (size_t)(64 * jtile) * QKD;
        float* kdst = KsB + buf * KS_SZ;
#pragma unroll
        for (int i = 0; i < 12; i++) {
            int c = tid + i * 256;
            int r = c / 48, col = (c % 48) * 4;
            cp_async16(kdst + r * KS_LD + col, ksrc + (size_t)r * QKD + col, true);
        }
        const float* vsrc = Vh + (size_t)(64 * jtile) * DV;
        float* vdst = VsB + buf * VS_SZ;
#pragma unroll
        for (int i = 0; i < 8; i++) {
            int c = tid + i * 256;
            int r = c >> 5, col = (c & 31) * 4;
            cp_async16(vdst + r * VS_LD + col, vsrc + (size_t)r * DV + col, true);
        }
    };

    load_kv(0, 0);
    cp_async_commit();

    for (int jt = 0; jt < NT; jt++) {
        const int buf = jt & 1;
        __syncthreads();
        if (jt + 1 < NT) { load_kv(jt + 1, buf ^ 1); cp_async_commit(); cp_async_wait<1>(); }
        else             { cp_async_wait<0>(); }
        __syncthreads();

        const float* Kst = KsB + buf * KS_SZ;
        const float* Vst = VsB + buf * VS_SZ;

        // ---- S = Q K^T (16 x 64 per warp) ----
        float sc[8][4];
#pragma unroll
        for (int njp = 0; njp < 4; njp++) {
            float s0[4] = {0.f, 0.f, 0.f, 0.f};
            float s1[4] = {0.f, 0.f, 0.f, 0.f};
            const float* kr0 = Kst + (size_t)((2 * njp) * 8 + g) * KS_LD;
            const float* kr1 = Kst + (size_t)((2 * njp + 1) * 8 + g) * KS_LD;
#pragma unroll
            for (int kg = 0; kg < 24; kg++) {
                uint32_t b0 = f2tf(kr0[8 * kg + t]);
                uint32_t b1 = f2tf(kr0[8 * kg + t + 4]);
                mma_tf32(s0, qa[kg], b0, b1);
                uint32_t b2 = f2tf(kr1[8 * kg + t]);
                uint32_t b3 = f2tf(kr1[8 * kg + t + 4]);
                mma_tf32(s1, qa[kg], b2, b3);
            }
#pragma unroll
            for (int e = 0; e < 4; e++) { sc[2 * njp][e] = s0[e]; sc[2 * njp + 1][e] = s1[e]; }
        }

        // ---- causal mask ----
#pragma unroll
        for (int nj = 0; nj < 8; nj++) {
            int colb = 64 * jt + 8 * nj + 2 * t;
            if (colb     > row0) sc[nj][0] = -1e30f;
            if (colb + 1 > row0) sc[nj][1] = -1e30f;
            if (colb     > row1) sc[nj][2] = -1e30f;
            if (colb + 1 > row1) sc[nj][3] = -1e30f;
        }

        // ---- online softmax (rows g and g+8) ----
        float tm0 = -1e30f, tm1 = -1e30f;
#pragma unroll
        for (int nj = 0; nj < 8; nj++) {
            tm0 = fmaxf(tm0, fmaxf(sc[nj][0], sc[nj][1]));
            tm1 = fmaxf(tm1, fmaxf(sc[nj][2], sc[nj][3]));
        }
        tm0 = fmaxf(tm0, __shfl_xor_sync(0xffffffffu, tm0, 1));
        tm0 = fmaxf(tm0, __shfl_xor_sync(0xffffffffu, tm0, 2));
        tm1 = fmaxf(tm1, __shfl_xor_sync(0xffffffffu, tm1, 1));
        tm1 = fmaxf(tm1, __shfl_xor_sync(0xffffffffu, tm1, 2));
        const float nm0 = fmaxf(m0, tm0), nm1 = fmaxf(m1, tm1);
        const float al0 = expf((m0 - nm0) * SM_SCALE);
        const float al1 = expf((m1 - nm1) * SM_SCALE);

        float rs0 = 0.f, rs1 = 0.f;
#pragma unroll
        for (int nj = 0; nj < 8; nj++) {
            float p0 = expf((sc[nj][0] - nm0) * SM_SCALE);
            float p1 = expf((sc[nj][1] - nm0) * SM_SCALE);
            float p2 = expf((sc[nj][2] - nm1) * SM_SCALE);
            float p3 = expf((sc[nj][3] - nm1) * SM_SCALE);
            rs0 += p0 + p1;
            rs1 += p2 + p3;
            uint2 u01; u01.x = f2tf(p0); u01.y = f2tf(p1);
            uint2 u23; u23.x = f2tf(p2); u23.y = f2tf(p3);
            *(uint2*)(Pw + g * PS_LD + 8 * nj + 2 * t)       = u01;
            *(uint2*)(Pw + (g + 8) * PS_LD + 8 * nj + 2 * t) = u23;
        }
        l0 = l0 * al0 + rs0;   // per-thread partial; quad-reduced after the loop
        l1 = l1 * al1 + rs1;
        m0 = nm0; m1 = nm1;
#pragma unroll
        for (int dj = 0; dj < 16; dj++) {
            o[dj][0] *= al0; o[dj][1] *= al0;
            o[dj][2] *= al1; o[dj][3] *= al1;
        }
        __syncwarp();

        // ---- O += P V ----
#pragma unroll
        for (int kg = 0; kg < 8; kg++) {
            uint32_t pa[4];
            pa[0] = __float_as_uint(Pw[g * PS_LD + 8 * kg + t]);
            pa[1] = __float_as_uint(Pw[(g + 8) * PS_LD + 8 * kg + t]);
            pa[2] = __float_as_uint(Pw[g * PS_LD + 8 * kg + t + 4]);
            pa[3] = __float_as_uint(Pw[(g + 8) * PS_LD + 8 * kg + t + 4]);
            const float* v0 = Vst + (size_t)(8 * kg + t) * VS_LD;
            const float* v1 = Vst + (size_t)(8 * kg + t + 4) * VS_LD;
#pragma unroll
            for (int dj = 0; dj < 16; dj += 2) {
                uint32_t b0 = f2tf(v0[8 * dj + g]);
                uint32_t b1 = f2tf(v1[8 * dj + g]);
                mma_tf32(o[dj], pa, b0, b1);
                uint32_t b2 = f2tf(v0[8 * (dj + 1) + g]);
                uint32_t b3 = f2tf(v1[8 * (dj + 1) + g]);
                mma_tf32(o[dj + 1], pa, b2, b3);
            }
        }
        __syncwarp();
    }

    // ---- FIX: reduce the softmax denominator across the quad (4 threads own
    // disjoint column subsets of the same rows) ----
    l0 += __shfl_xor_sync(0xffffffffu, l0, 1);
    l0 += __shfl_xor_sync(0xffffffffu, l0, 2);
    l1 += __shfl_xor_sync(0xffffffffu, l1, 1);
    l1 += __shfl_xor_sync(0xffffffffu, l1, 2);

    // ---- normalize + store ----
    const float inv0 = 1.f / l0, inv1 = 1.f / l1;
    float* or0 = Out + (size_t)row0 * Hh + h * DV;
    float* or1 = Out + (size_t)row1 * Hh + h * DV;
#pragma unroll
    for (int dj = 0; dj < 16; dj++) {
        float2 w0; w0.x = o[dj][0] * inv0; w0.y = o[dj][1] * inv0;
        float2 w1; w1.x = o[dj][2] * inv1; w1.y = o[dj][3] * inv1;
        *(float2*)(or0 + 8 * dj + 2 * t) = w0;
        *(float2*)(or1 + 8 * dj + 2 * t) = w1;
    }
}

// ---------------- rmsnorm over first K cols of each row ----------------
__global__ void rmsnorm_kernel(const float* __restrict__ X, const float* __restrict__ w,
                               float* __restrict__ Y, int K, int ldx, int ldy) {
    const int row = blockIdx.x;
    const float* x = X + (size_t)row * ldx;
    float* y = Y + (size_t)row * ldy;
    float ss = 0.f;
    for (int j = threadIdx.x; j < K; j += blockDim.x) { float v = x[j]; ss += v * v; }
    __shared__ float red[256];
    red[threadIdx.x] = ss;
    __syncthreads();
    for (int s = 128; s > 0; s >>= 1) {
        if (threadIdx.x < s) red[threadIdx.x] += red[threadIdx.x + s];
        __syncthreads();
    }
    float inv = rsqrtf(red[0] / (float)K + 1e-6f);
    for (int j = threadIdx.x; j < K; j += blockDim.x) y[j] = x[j] * inv * w[j];
}

// ---------------- build Q[h][s][0..192) with RoPE on last 64 ----------------
__global__ void build_q(const float* __restrict__ q, const float* __restrict__ freqs,
                        float* __restrict__ Qb) {
    const int s = blockIdx.x, h = blockIdx.y, d = threadIdx.x;
    const float* qr = q + (size_t)s * (NH * QKD) + h * QKD;
    float val;
    if (d < DN) {
        val = qr[d];
    } else {
        int u = d - DN, t = u >> 1;
        float f = freqs[s * (DR / 2) + t];
        float c = cosf(f), sn = sinf(f);
        float xr = qr[DN + 2 * t], xi = qr[DN + 2 * t + 1];
        val = (u & 1) ? (xr * sn + xi * c) : (xr * c - xi * sn);
    }
    Qb[((size_t)h * S + s) * QKD + d] = val;
}

// ---------------- build K[h][s][0..192) and V[h][s][0..128) ----------------
__global__ void build_kv(const float* __restrict__ kv, const float* __restrict__ ckv,
                         const float* __restrict__ freqs,
                         float* __restrict__ Kb, float* __restrict__ Vb) {
    const int s = blockIdx.x, h = blockIdx.y, d = threadIdx.x;
    const float* kvr = kv + (size_t)s * (NH * (DN + DV)) + h * (DN + DV);
    if (d < DN) {
        Kb[((size_t)h * S + s) * QKD + d] = kvr[d];
    } else if (d < QKD) {
        int u = d - DN, t = u >> 1;
        float f = freqs[s * (DR / 2) + t];
        float c = cosf(f), sn = sinf(f);
        const float* kr = ckv + (size_t)s * CKVW + RKV;
        float xr = kr[2 * t], xi = kr[2 * t + 1];
        Kb[((size_t)h * S + s) * QKD + d] = (u & 1) ? (xr * sn + xi * c) : (xr * c - xi * sn);
    } else {
        int dv = d - QKD;
        Vb[((size_t)h * S + s) * DV + dv] = kvr[DN + dv];
    }
}

// ---------------- host ----------------
static float* sym_addr(const void* symbol) {
    void* p = nullptr;
    cudaGetSymbolAddress(&p, symbol);
    return (float*)p;
}

extern "C" void kernel_launch(void* const* d_in, const int* in_sizes, int n_in,
                              void* d_out, int out_size) {
    const float* hidden    = (const float*)d_in[0];
    const float* freqs     = (const float*)d_in[1];
    const float* q_a_w     = (const float*)d_in[2];
    const float* q_a_ln_w  = (const float*)d_in[3];
    const float* q_b_w     = (const float*)d_in[4];
    const float* kv_a_w    = (const float*)d_in[5];
    const float* kv_a_ln_w = (const float*)d_in[6];
    const float* kv_b_w    = (const float*)d_in[7];
    const float* o_w       = (const float*)d_in[8];
    float* out = (float*)d_out;

    float* qa   = sym_addr(g_qa);
    float* qan  = sym_addr(g_qan);
    float* q    = sym_addr(g_q);
    float* ckv  = sym_addr(g_ckv);
    float* ckvn = sym_addr(g_ckvn);
    float* kv   = sym_addr(g_kv);
    float* Qb   = sym_addr(g_Q);
    float* Kb   = sym_addr(g_K);
    float* Vb   = sym_addr(g_V);
    float* attn = sym_addr(g_attn);

    cudaFuncSetAttribute(flash_attn, cudaFuncAttributeMaxDynamicSharedMemorySize, FLASH_SMEM);

    dim3 blk(256);

    // 1) q_a = hidden @ q_a_w^T       [2048,1536]
    gemm_nt_tc<<<dim3(RQ / 128, S / 128), blk>>>(hidden, q_a_w, qa, S, RQ, Hh);
    // 2) rmsnorm(q_a)
    rmsnorm_kernel<<<S, 256>>>(qa, q_a_ln_w, qan, RQ, RQ, RQ);
    // 3) q = qan @ q_b_w^T            [2048,6144]
    gemm_nt_tc<<<dim3(NH * QKD / 128, S / 128), blk>>>(qan, q_b_w, q, S, NH * QKD, RQ);
    // 4) ckv = hidden @ kv_a_w^T      [2048,576]
    gemm_nt_tc<<<dim3((CKVW + 127) / 128, S / 128), blk>>>(hidden, kv_a_w, ckv, S, CKVW, Hh);
    // 5) rmsnorm(ckv[:, :512])
    rmsnorm_kernel<<<S, 256>>>(ckv, kv_a_ln_w, ckvn, RKV, CKVW, RKV);
    // 6) kv = ckvn @ kv_b_w^T         [2048,8192]
    gemm_nt_tc<<<dim3(NH * (DN + DV) / 128, S / 128), blk>>>(ckvn, kv_b_w, kv, S, NH * (DN + DV), RKV);
    // 7) assemble Q with RoPE
    build_q<<<dim3(S, NH), QKD>>>(q, freqs, Qb);
    // 8) assemble K (RoPE) and V
    build_kv<<<dim3(S, NH), QKD + DV>>>(kv, ckv, freqs, Kb, Vb);
    // 9-11) fused flash attention -> g_attn [s, h*128+d]
    flash_attn<<<dim3(S / 128, NH), blk, FLASH_SMEM>>>(Qb, Kb, Vb, attn);
    // 12) out = attn @ o_w^T          [2048,4096]
    gemm_nt_tc<<<dim3(Hh / 128, S / 128), blk>>>(attn, o_w, out, S, Hh, Hh);
}

// round 7
// speedup vs baseline: 2.1648x; 1.0552x over previous
#include <cuda_runtime.h>
#include <cuda_bf16.h>
#include <mma.h>
#include <math.h>
#include <cstdint>
#include <cstddef>
using namespace nvcuda;

// ---------------- problem constants ----------------
#define S    2048
#define Hh   4096
#define NH   32
#define DN   128
#define DR   64
#define DV   128
#define QKD  192          // DN + DR
#define RQ   1536
#define RKV  512
#define CKVW 576          // RKV + DR

#define BM 128
#define BN 128
#define BK 16
#define LDT 20

#define SM_SCALE 0.072168783648703220563f   // 192^-0.5

// ---------------- scratch (device globals; allocation-free) ----------------
__device__ float g_qa  [S * RQ];
__device__ float g_qan [S * RQ];
__device__ float g_q   [S * NH * QKD];
__device__ float g_ckv [S * CKVW];
__device__ float g_ckvn[S * RKV];
__device__ float g_kv  [S * NH * (DN+DV)];
__device__ float g_Q   [(size_t)NH * S * QKD];
__device__ float g_K   [(size_t)NH * S * QKD];
__device__ float g_V   [(size_t)NH * S * DV];
__device__ float g_attn[S * Hh];
// tf32-pre-rounded copies of inputs (weights + hidden)
__device__ float g_hid [S * Hh];
__device__ float g_qaw [RQ * Hh];
__device__ float g_qbw [NH * QKD * RQ];
__device__ float g_kvaw[CKVW * Hh];
__device__ float g_kvbw[NH * (DN+DV) * RKV];
__device__ float g_ow  [(size_t)Hh * Hh];

// ---------------- cp.async helpers ----------------
__device__ __forceinline__ void cp_async16(void* smem, const void* gmem, bool pred) {
    unsigned int s = (unsigned int)__cvta_generic_to_shared(smem);
    int sz = pred ? 16 : 0;
    asm volatile("cp.async.cg.shared.global [%0], [%1], 16, %2;\n" :: "r"(s), "l"(gmem), "r"(sz));
}
__device__ __forceinline__ void cp_async_commit() { asm volatile("cp.async.commit_group;\n"); }
template<int N_> __device__ __forceinline__ void cp_async_wait() { asm volatile("cp.async.wait_group %0;\n" :: "n"(N_)); }

// ---------------- tf32 helpers ----------------
__device__ __forceinline__ uint32_t f2tf(float x) {
    uint32_t r; asm("cvt.rna.tf32.f32 %0, %1;" : "=r"(r) : "f"(x)); return r;
}
__device__ __forceinline__ float tf32r(float x) { return __uint_as_float(f2tf(x)); }
__device__ __forceinline__ void mma_tf32(float* c, const uint32_t* a, uint32_t b0, uint32_t b1) {
    asm("mma.sync.aligned.m16n8k8.row.col.f32.tf32.tf32.f32 "
        "{%0,%1,%2,%3},{%4,%5,%6,%7},{%8,%9},{%0,%1,%2,%3};"
        : "+f"(c[0]), "+f"(c[1]), "+f"(c[2]), "+f"(c[3])
        : "r"(a[0]), "r"(a[1]), "r"(a[2]), "r"(a[3]), "r"(b0), "r"(b1));
}

typedef wmma::fragment<wmma::matrix_a, 16,16,8, wmma::precision::tf32, wmma::row_major> FragA;
typedef wmma::fragment<wmma::matrix_b, 16,16,8, wmma::precision::tf32, wmma::col_major> FragBc;
typedef wmma::fragment<wmma::accumulator, 16,16,8, float> FragC;

// ---------------- elementwise tf32 rounding (float4 vectorized) ----------------
__global__ void round_tf32_kernel(const float4* __restrict__ in, float4* __restrict__ out, int n4) {
    int i = blockIdx.x * blockDim.x + threadIdx.x;
    if (i < n4) {
        float4 v = in[i];
        v.x = tf32r(v.x); v.y = tf32r(v.y); v.z = tf32r(v.z); v.w = tf32r(v.w);
        out[i] = v;
    }
}

// ============ generic NT GEMM: C[M,N] = A[M,K] * B[N,K]^T ============
// Inputs MUST already be tf32-rounded. No cvt in the inner loop.
__global__ __launch_bounds__(256, 2)
void gemm_nt_tc(const float* __restrict__ A, const float* __restrict__ B,
                float* __restrict__ C, int M, int N, int K) {
    __shared__ alignas(16) float As[2][BM * LDT];
    __shared__ alignas(16) float Bs[2][BN * LDT];
    const int tid = threadIdx.x;
    const int warp = tid >> 5;
    const int wm = warp & 1, wn = warp >> 1;
    const int bm = blockIdx.y * BM, bn = blockIdx.x * BN;

    FragC c[4][2];
#pragma unroll
    for (int i = 0; i < 4; i++)
#pragma unroll
        for (int j = 0; j < 2; j++) wmma::fill_fragment(c[i][j], 0.f);

    const int T = K / BK;
    auto load_tiles = [&](int kt, int buf) {
        const int k0 = kt * BK;
#pragma unroll
        for (int u = 0; u < 2; u++) {
            int f = tid + u * 256;
            int row = f >> 2, col = (f & 3) * 4;
            cp_async16(&As[buf][row * LDT + col], A + (size_t)(bm + row) * K + k0 + col, true);
        }
#pragma unroll
        for (int u = 0; u < 2; u++) {
            int f = tid + u * 256;
            int row = f >> 2, col = (f & 3) * 4;
            bool p = (bn + row) < N;
            cp_async16(&Bs[buf][row * LDT + col],
                       B + (size_t)(p ? (bn + row) : 0) * K + k0 + col, p);
        }
        cp_async_commit();
    };

    load_tiles(0, 0);
    for (int t = 0; t < T; t++) {
        const int buf = t & 1;
        if (t + 1 < T) { load_tiles(t + 1, buf ^ 1); cp_async_wait<1>(); }
        else           { cp_async_wait<0>(); }
        __syncthreads();
#pragma unroll
        for (int kk = 0; kk < BK; kk += 8) {
            FragA a[4]; FragBc b[2];
#pragma unroll
            for (int i = 0; i < 4; i++)
                wmma::load_matrix_sync(a[i], &As[buf][(wm * 64 + i * 16) * LDT + kk], LDT);
#pragma unroll
            for (int j = 0; j < 2; j++)
                wmma::load_matrix_sync(b[j], &Bs[buf][(wn * 32 + j * 16) * LDT + kk], LDT);
#pragma unroll
            for (int i = 0; i < 4; i++)
#pragma unroll
                for (int j = 0; j < 2; j++)
                    wmma::mma_sync(c[i][j], a[i], b[j], c[i][j]);
        }
        __syncthreads();
    }
#pragma unroll
    for (int i = 0; i < 4; i++)
#pragma unroll
        for (int j = 0; j < 2; j++) {
            int gm = bm + wm * 64 + i * 16;
            int gn = bn + wn * 32 + j * 16;
            if (gn + 16 <= N)
                wmma::store_matrix_sync(&C[(size_t)gm * N + gn], c[i][j], N, wmma::mem_row_major);
        }
}

// ================== fused flash attention (tf32 mma.sync) ==================
// Q/K/V are pre-rounded to tf32; only P needs cvt (fresh exp values).
#define KS_LD 196
#define VS_LD 136
#define PS_LD 68
#define KS_SZ (64 * KS_LD)
#define VS_SZ (64 * VS_LD)
#define PS_SZ (16 * PS_LD)
#define FLASH_SMEM ((2 * KS_SZ + 2 * VS_SZ + 8 * PS_SZ) * 4)

__global__ __launch_bounds__(256, 1)
void flash_attn(const float* __restrict__ Qb, const float* __restrict__ Kb,
                const float* __restrict__ Vb, float* __restrict__ Out) {
    extern __shared__ float sm[];
    float* KsB = sm;
    float* VsB = sm + 2 * KS_SZ;
    float* PsB = sm + 2 * KS_SZ + 2 * VS_SZ;

    const int qt   = (int)(gridDim.x - 1 - blockIdx.x);  // heavy tiles first
    const int h    = blockIdx.y;
    const int bm   = qt * 128;
    const int tid  = threadIdx.x;
    const int warp = tid >> 5, lane = tid & 31;
    const int g    = lane >> 2, t = lane & 3;
    const int row0 = bm + warp * 16 + g;
    const int row1 = row0 + 8;

    const float* Qh = Qb + (size_t)h * S * QKD;
    const float* Kh = Kb + (size_t)h * S * QKD;
    const float* Vh = Vb + (size_t)h * S * DV;
    float* Pw = PsB + warp * PS_SZ;

    // ---- preload Q fragments (already tf32-rounded) ----
    uint32_t qa[24][4];
    {
        const float* q0 = Qh + (size_t)row0 * QKD;
        const float* q1 = Qh + (size_t)row1 * QKD;
#pragma unroll
        for (int kg = 0; kg < 24; kg++) {
            qa[kg][0] = __float_as_uint(__ldg(q0 + 8 * kg + t));
            qa[kg][1] = __float_as_uint(__ldg(q1 + 8 * kg + t));
            qa[kg][2] = __float_as_uint(__ldg(q0 + 8 * kg + t + 4));
            qa[kg][3] = __float_as_uint(__ldg(q1 + 8 * kg + t + 4));
        }
    }

    float o[16][4];
#pragma unroll
    for (int i = 0; i < 16; i++) { o[i][0] = o[i][1] = o[i][2] = o[i][3] = 0.f; }
    float m0 = -1e30f, m1 = -1e30f, l0 = 0.f, l1 = 0.f;

    const int NT = 2 * qt + 2;

    auto load_kv = [&](int jtile, int buf) {
        const float* ksrc = Kh + (size_t)(64 * jtile) * QKD;
        float* kdst = KsB + buf * KS_SZ;
#pragma unroll
        for (int i = 0; i < 12; i++) {
            int c = tid + i * 256;
            int r = c / 48, col = (c % 48) * 4;
            cp_async16(kdst + r * KS_LD + col, ksrc + (size_t)r * QKD + col, true);
        }
        const float* vsrc = Vh + (size_t)(64 * jtile) * DV;
        float* vdst = VsB + buf * VS_SZ;
#pragma unroll
        for (int i = 0; i < 8; i++) {
            int c = tid + i * 256;
            int r = c >> 5, col = (c & 31) * 4;
            cp_async16(vdst + r * VS_LD + col, vsrc + (size_t)r * DV + col, true);
        }
    };

    load_kv(0, 0);
    cp_async_commit();

    for (int jt = 0; jt < NT; jt++) {
        const int buf = jt & 1;
        __syncthreads();
        if (jt + 1 < NT) { load_kv(jt + 1, buf ^ 1); cp_async_commit(); cp_async_wait<1>(); }
        else             { cp_async_wait<0>(); }
        __syncthreads();

        const float* Kst = KsB + buf * KS_SZ;
        const float* Vst = VsB + buf * VS_SZ;

        // ---- S = Q K^T (16 x 64 per warp) ----
        float sc[8][4];
#pragma unroll
        for (int njp = 0; njp < 4; njp++) {
            float s0[4] = {0.f, 0.f, 0.f, 0.f};
            float s1[4] = {0.f, 0.f, 0.f, 0.f};
            const float* kr0 = Kst + (size_t)((2 * njp) * 8 + g) * KS_LD;
            const float* kr1 = Kst + (size_t)((2 * njp + 1) * 8 + g) * KS_LD;
#pragma unroll
            for (int kg = 0; kg < 24; kg++) {
                uint32_t b0 = __float_as_uint(kr0[8 * kg + t]);
                uint32_t b1 = __float_as_uint(kr0[8 * kg + t + 4]);
                mma_tf32(s0, qa[kg], b0, b1);
                uint32_t b2 = __float_as_uint(kr1[8 * kg + t]);
                uint32_t b3 = __float_as_uint(kr1[8 * kg + t + 4]);
                mma_tf32(s1, qa[kg], b2, b3);
            }
#pragma unroll
            for (int e = 0; e < 4; e++) { sc[2 * njp][e] = s0[e]; sc[2 * njp + 1][e] = s1[e]; }
        }

        // ---- causal mask ----
#pragma unroll
        for (int nj = 0; nj < 8; nj++) {
            int colb = 64 * jt + 8 * nj + 2 * t;
            if (colb     > row0) sc[nj][0] = -1e30f;
            if (colb + 1 > row0) sc[nj][1] = -1e30f;
            if (colb     > row1) sc[nj][2] = -1e30f;
            if (colb + 1 > row1) sc[nj][3] = -1e30f;
        }

        // ---- online softmax (rows g and g+8) ----
        float tm0 = -1e30f, tm1 = -1e30f;
#pragma unroll
        for (int nj = 0; nj < 8; nj++) {
            tm0 = fmaxf(tm0, fmaxf(sc[nj][0], sc[nj][1]));
            tm1 = fmaxf(tm1, fmaxf(sc[nj][2], sc[nj][3]));
        }
        tm0 = fmaxf(tm0, __shfl_xor_sync(0xffffffffu, tm0, 1));
        tm0 = fmaxf(tm0, __shfl_xor_sync(0xffffffffu, tm0, 2));
        tm1 = fmaxf(tm1, __shfl_xor_sync(0xffffffffu, tm1, 1));
        tm1 = fmaxf(tm1, __shfl_xor_sync(0xffffffffu, tm1, 2));
        const float nm0 = fmaxf(m0, tm0), nm1 = fmaxf(m1, tm1);
        const float al0 = expf((m0 - nm0) * SM_SCALE);
        const float al1 = expf((m1 - nm1) * SM_SCALE);

        float rs0 = 0.f, rs1 = 0.f;
#pragma unroll
        for (int nj = 0; nj < 8; nj++) {
            float p0 = expf((sc[nj][0] - nm0) * SM_SCALE);
            float p1 = expf((sc[nj][1] - nm0) * SM_SCALE);
            float p2 = expf((sc[nj][2] - nm1) * SM_SCALE);
            float p3 = expf((sc[nj][3] - nm1) * SM_SCALE);
            rs0 += p0 + p1;
            rs1 += p2 + p3;
            uint2 u01; u01.x = f2tf(p0); u01.y = f2tf(p1);
            uint2 u23; u23.x = f2tf(p2); u23.y = f2tf(p3);
            *(uint2*)(Pw + g * PS_LD + 8 * nj + 2 * t)       = u01;
            *(uint2*)(Pw + (g + 8) * PS_LD + 8 * nj + 2 * t) = u23;
        }
        l0 = l0 * al0 + rs0;   // per-thread partial; quad-reduced after the loop
        l1 = l1 * al1 + rs1;
        m0 = nm0; m1 = nm1;
#pragma unroll
        for (int dj = 0; dj < 16; dj++) {
            o[dj][0] *= al0; o[dj][1] *= al0;
            o[dj][2] *= al1; o[dj][3] *= al1;
        }
        __syncwarp();

        // ---- O += P V ----
#pragma unroll
        for (int kg = 0; kg < 8; kg++) {
            uint32_t pa[4];
            pa[0] = __float_as_uint(Pw[g * PS_LD + 8 * kg + t]);
            pa[1] = __float_as_uint(Pw[(g + 8) * PS_LD + 8 * kg + t]);
            pa[2] = __float_as_uint(Pw[g * PS_LD + 8 * kg + t + 4]);
            pa[3] = __float_as_uint(Pw[(g + 8) * PS_LD + 8 * kg + t + 4]);
            const float* v0 = Vst + (size_t)(8 * kg + t) * VS_LD;
            const float* v1 = Vst + (size_t)(8 * kg + t + 4) * VS_LD;
#pragma unroll
            for (int dj = 0; dj < 16; dj += 2) {
                uint32_t b0 = __float_as_uint(v0[8 * dj + g]);
                uint32_t b1 = __float_as_uint(v1[8 * dj + g]);
                mma_tf32(o[dj], pa, b0, b1);
                uint32_t b2 = __float_as_uint(v0[8 * (dj + 1) + g]);
                uint32_t b3 = __float_as_uint(v1[8 * (dj + 1) + g]);
                mma_tf32(o[dj + 1], pa, b2, b3);
            }
        }
        __syncwarp();
    }

    // ---- quad reduction of softmax denominator ----
    l0 += __shfl_xor_sync(0xffffffffu, l0, 1);
    l0 += __shfl_xor_sync(0xffffffffu, l0, 2);
    l1 += __shfl_xor_sync(0xffffffffu, l1, 1);
    l1 += __shfl_xor_sync(0xffffffffu, l1, 2);

    // ---- normalize + store (tf32-rounded: feeds final GEMM as A) ----
    const float inv0 = 1.f / l0, inv1 = 1.f / l1;
    float* or0 = Out + (size_t)row0 * Hh + h * DV;
    float* or1 = Out + (size_t)row1 * Hh + h * DV;
#pragma unroll
    for (int dj = 0; dj < 16; dj++) {
        float2 w0; w0.x = tf32r(o[dj][0] * inv0); w0.y = tf32r(o[dj][1] * inv0);
        float2 w1; w1.x = tf32r(o[dj][2] * inv1); w1.y = tf32r(o[dj][3] * inv1);
        *(float2*)(or0 + 8 * dj + 2 * t) = w0;
        *(float2*)(or1 + 8 * dj + 2 * t) = w1;
    }
}

// ---------------- rmsnorm over first K cols; output tf32-rounded ----------------
__global__ void rmsnorm_kernel(const float* __restrict__ X, const float* __restrict__ w,
                               float* __restrict__ Y, int K, int ldx, int ldy) {
    const int row = blockIdx.x;
    const float* x = X + (size_t)row * ldx;
    float* y = Y + (size_t)row * ldy;
    float ss = 0.f;
    for (int j = threadIdx.x; j < K; j += blockDim.x) { float v = x[j]; ss += v * v; }
    __shared__ float red[256];
    red[threadIdx.x] = ss;
    __syncthreads();
    for (int s = 128; s > 0; s >>= 1) {
        if (threadIdx.x < s) red[threadIdx.x] += red[threadIdx.x + s];
        __syncthreads();
    }
    float inv = rsqrtf(red[0] / (float)K + 1e-6f);
    for (int j = threadIdx.x; j < K; j += blockDim.x) y[j] = tf32r(x[j] * inv * w[j]);
}

// ---------------- build Q[h][s][0..192) with RoPE; tf32-rounded ----------------
__global__ void build_q(const float* __restrict__ q, const float* __restrict__ freqs,
                        float* __restrict__ Qb) {
    const int s = blockIdx.x, h = blockIdx.y, d = threadIdx.x;
    const float* qr = q + (size_t)s * (NH * QKD) + h * QKD;
    float val;
    if (d < DN) {
        val = qr[d];
    } else {
        int u = d - DN, t = u >> 1;
        float f = freqs[s * (DR / 2) + t];
        float c = cosf(f), sn = sinf(f);
        float xr = qr[DN + 2 * t], xi = qr[DN + 2 * t + 1];
        val = (u & 1) ? (xr * sn + xi * c) : (xr * c - xi * sn);
    }
    Qb[((size_t)h * S + s) * QKD + d] = tf32r(val);
}

// ---------------- build K and V; tf32-rounded ----------------
__global__ void build_kv(const float* __restrict__ kv, const float* __restrict__ ckv,
                         const float* __restrict__ freqs,
                         float* __restrict__ Kb, float* __restrict__ Vb) {
    const int s = blockIdx.x, h = blockIdx.y, d = threadIdx.x;
    const float* kvr = kv + (size_t)s * (NH * (DN + DV)) + h * (DN + DV);
    if (d < DN) {
        Kb[((size_t)h * S + s) * QKD + d] = tf32r(kvr[d]);
    } else if (d < QKD) {
        int u = d - DN, t = u >> 1;
        float f = freqs[s * (DR / 2) + t];
        float c = cosf(f), sn = sinf(f);
        const float* kr = ckv + (size_t)s * CKVW + RKV;
        float xr = kr[2 * t], xi = kr[2 * t + 1];
        Kb[((size_t)h * S + s) * QKD + d] = tf32r((u & 1) ? (xr * sn + xi * c) : (xr * c - xi * sn));
    } else {
        int dv = d - QKD;
        Vb[((size_t)h * S + s) * DV + dv] = tf32r(kvr[DN + dv]);
    }
}

// ---------------- host ----------------
static float* sym_addr(const void* symbol) {
    void* p = nullptr;
    cudaGetSymbolAddress(&p, symbol);
    return (float*)p;
}

static void launch_round(const float* src, float* dst, size_t n) {
    int n4 = (int)(n / 4);
    round_tf32_kernel<<<(n4 + 255) / 256, 256>>>((const float4*)src, (float4*)dst, n4);
}

extern "C" void kernel_launch(void* const* d_in, const int* in_sizes, int n_in,
                              void* d_out, int out_size) {
    const float* hidden    = (const float*)d_in[0];
    const float* freqs     = (const float*)d_in[1];
    const float* q_a_w     = (const float*)d_in[2];
    const float* q_a_ln_w  = (const float*)d_in[3];
    const float* q_b_w     = (const float*)d_in[4];
    const float* kv_a_w    = (const float*)d_in[5];
    const float* kv_a_ln_w = (const float*)d_in[6];
    const float* kv_b_w    = (const float*)d_in[7];
    const float* o_w       = (const float*)d_in[8];
    float* out = (float*)d_out;

    float* qa   = sym_addr(g_qa);
    float* qan  = sym_addr(g_qan);
    float* q    = sym_addr(g_q);
    float* ckv  = sym_addr(g_ckv);
    float* ckvn = sym_addr(g_ckvn);
    float* kv   = sym_addr(g_kv);
    float* Qb   = sym_addr(g_Q);
    float* Kb   = sym_addr(g_K);
    float* Vb   = sym_addr(g_V);
    float* attn = sym_addr(g_attn);
    float* hid  = sym_addr(g_hid);
    float* qaw  = sym_addr(g_qaw);
    float* qbw  = sym_addr(g_qbw);
    float* kvaw = sym_addr(g_kvaw);
    float* kvbw = sym_addr(g_kvbw);
    float* ow   = sym_addr(g_ow);

    cudaFuncSetAttribute(flash_attn, cudaFuncAttributeMaxDynamicSharedMemorySize, FLASH_SMEM);

    dim3 blk(256);

    // 0) pre-round inputs to tf32 (rna), once per call
    launch_round(hidden, hid,  (size_t)S * Hh);
    launch_round(q_a_w,  qaw,  (size_t)RQ * Hh);
    launch_round(q_b_w,  qbw,  (size_t)NH * QKD * RQ);
    launch_round(kv_a_w, kvaw, (size_t)CKVW * Hh);
    launch_round(kv_b_w, kvbw, (size_t)NH * (DN + DV) * RKV);
    launch_round(o_w,    ow,   (size_t)Hh * Hh);

    // 1) q_a = hid @ qaw^T       [2048,1536]
    gemm_nt_tc<<<dim3(RQ / 128, S / 128), blk>>>(hid, qaw, qa, S, RQ, Hh);
    // 2) rmsnorm(q_a) -> tf32
    rmsnorm_kernel<<<S, 256>>>(qa, q_a_ln_w, qan, RQ, RQ, RQ);
    // 3) q = qan @ qbw^T         [2048,6144]
    gemm_nt_tc<<<dim3(NH * QKD / 128, S / 128), blk>>>(qan, qbw, q, S, NH * QKD, RQ);
    // 4) ckv = hid @ kvaw^T      [2048,576]
    gemm_nt_tc<<<dim3((CKVW + 127) / 128, S / 128), blk>>>(hid, kvaw, ckv, S, CKVW, Hh);
    // 5) rmsnorm(ckv[:, :512]) -> tf32
    rmsnorm_kernel<<<S, 256>>>(ckv, kv_a_ln_w, ckvn, RKV, CKVW, RKV);
    // 6) kv = ckvn @ kvbw^T      [2048,8192]
    gemm_nt_tc<<<dim3(NH * (DN + DV) / 128, S / 128), blk>>>(ckvn, kvbw, kv, S, NH * (DN + DV), RKV);
    // 7) assemble Q with RoPE (tf32)
    build_q<<<dim3(S, NH), QKD>>>(q, freqs, Qb);
    // 8) assemble K (RoPE) and V (tf32)
    build_kv<<<dim3(S, NH), QKD + DV>>>(kv, ckv, freqs, Kb, Vb);
    // 9-11) fused flash attention -> g_attn (tf32-rounded)
    flash_attn<<<dim3(S / 128, NH), blk, FLASH_SMEM>>>(Qb, Kb, Vb, attn);
    // 12) out = attn @ ow^T      [2048,4096]
    gemm_nt_tc<<<dim3(Hh / 128, S / 128), blk>>>(attn, ow, out, S, Hh, Hh);
}

// round 9
// speedup vs baseline: 3.2347x; 1.4942x over previous
#include <cuda_runtime.h>
#include <cuda_bf16.h>
#include <math.h>
#include <cstdint>
#include <cstddef>

// ---------------- problem constants ----------------
#define S    2048
#define Hh   4096
#define NH   32
#define DN   128
#define DR   64
#define DV   128
#define QKD  192          // DN + DR
#define RQ   1536
#define RKV  512
#define CKVW 576          // RKV + DR

#define SM_SCALE 0.072168783648703220563f   // 192^-0.5

// ---- big GEMM tiling ----
#define BM 128
#define BN 256
#define BK 16
#define LDT 20
#define STG 3
#define AS_SZ (BM * LDT)          // 2560 floats
#define BS_SZ (BN * LDT)          // 5120 floats
#define GEMM_SMEM (STG * (AS_SZ + BS_SZ) * 4)   // 92160 B

// ---------------- scratch (device globals; allocation-free) ----------------
__device__ float g_qa  [S * RQ];
__device__ float g_qan [S * RQ];
__device__ float g_q   [S * NH * QKD];
__device__ float g_ckv [S * CKVW];
__device__ float g_ckvn[S * RKV];
__device__ float g_kv  [S * NH * (DN+DV)];
__device__ float g_Q   [(size_t)NH * S * QKD];
__device__ float g_K   [(size_t)NH * S * QKD];
__device__ float g_V   [(size_t)NH * S * DV];
__device__ float g_attn[S * Hh];
// tf32-pre-rounded copies of inputs (weights + hidden)
__device__ float g_hid [S * Hh];
__device__ float g_qaw [RQ * Hh];
__device__ float g_qbw [NH * QKD * RQ];
__device__ float g_kvaw[CKVW * Hh];
__device__ float g_kvbw[NH * (DN+DV) * RKV];
__device__ float g_ow  [(size_t)Hh * Hh];

// ---------------- cp.async helpers ----------------
__device__ __forceinline__ void cp_async16(void* smem, const void* gmem, bool pred) {
    unsigned int s = (unsigned int)__cvta_generic_to_shared(smem);
    int sz = pred ? 16 : 0;
    asm volatile("cp.async.cg.shared.global [%0], [%1], 16, %2;\n" :: "r"(s), "l"(gmem), "r"(sz));
}
__device__ __forceinline__ void cp_async_commit() { asm volatile("cp.async.commit_group;\n"); }
template<int N_> __device__ __forceinline__ void cp_async_wait() { asm volatile("cp.async.wait_group %0;\n" :: "n"(N_)); }

// ---------------- tf32 helpers ----------------
__device__ __forceinline__ uint32_t f2tf(float x) {
    uint32_t r; asm("cvt.rna.tf32.f32 %0, %1;" : "=r"(r) : "f"(x)); return r;
}
__device__ __forceinline__ float tf32r(float x) { return __uint_as_float(f2tf(x)); }
__device__ __forceinline__ void mma_tf32(float* c, const uint32_t* a, uint32_t b0, uint32_t b1) {
    asm("mma.sync.aligned.m16n8k8.row.col.f32.tf32.tf32.f32 "
        "{%0,%1,%2,%3},{%4,%5,%6,%7},{%8,%9},{%0,%1,%2,%3};"
        : "+f"(c[0]), "+f"(c[1]), "+f"(c[2]), "+f"(c[3])
        : "r"(a[0]), "r"(a[1]), "r"(a[2]), "r"(a[3]), "r"(b0), "r"(b1));
}

// ---------------- elementwise tf32 rounding (float4 vectorized) ----------------
__global__ void round_tf32_kernel(const float4* __restrict__ in, float4* __restrict__ out, int n4) {
    int i = blockIdx.x * blockDim.x + threadIdx.x;
    if (i < n4) {
        float4 v = in[i];
        v.x = tf32r(v.x); v.y = tf32r(v.y); v.z = tf32r(v.z); v.w = tf32r(v.w);
        out[i] = v;
    }
}

// ============ big NT GEMM: C[M,N] = A[M,K] * B[N,K]^T (raw mma, tf32-in) ============
// 128x256 block tile, BK=16, 3-stage cp.async, 8 warps in 2(M)x4(N), warp tile 64x64.
// Inputs must be tf32-pre-rounded. M must be a multiple of 128; N even; K multiple of 16.
__global__ __launch_bounds__(256, 1)
void gemm_nt_big(const float* __restrict__ A, const float* __restrict__ B,
                 float* __restrict__ C, int M, int N, int K) {
    extern __shared__ float smx[];
    const int tid  = threadIdx.x;
    const int warp = tid >> 5, lane = tid & 31;
    const int g    = lane >> 2, t = lane & 3;
    const int wm   = warp >> 2, wn = warp & 3;
    const int bm   = blockIdx.y * BM, bn = blockIdx.x * BN;

    float c[4][8][4];
#pragma unroll
    for (int i = 0; i < 4; i++)
#pragma unroll
        for (int j = 0; j < 8; j++) { c[i][j][0] = c[i][j][1] = c[i][j][2] = c[i][j][3] = 0.f; }

    const int T = K / BK;

    auto load_stage = [&](int kt, int stg) {
        float* As = smx + stg * (AS_SZ + BS_SZ);
        float* Bs = As + AS_SZ;
        const int k0 = kt * BK;
#pragma unroll
        for (int u = 0; u < 2; u++) {          // A: 128x16 = 512 16B-chunks
            int f = tid + u * 256;
            int row = f >> 2, col = (f & 3) * 4;
            cp_async16(&As[row * LDT + col], A + (size_t)(bm + row) * K + k0 + col, true);
        }
#pragma unroll
        for (int u = 0; u < 4; u++) {          // B: 256x16 = 1024 chunks
            int f = tid + u * 256;
            int row = f >> 2, col = (f & 3) * 4;
            bool p = (bn + row) < N;
            cp_async16(&Bs[row * LDT + col],
                       B + (size_t)(p ? (bn + row) : 0) * K + k0 + col, p);
        }
        cp_async_commit();
    };

    load_stage(0, 0);
    if (T > 1) load_stage(1, 1); else cp_async_commit();

    for (int kt = 0; kt < T; kt++) {
        cp_async_wait<STG - 2>();
        __syncthreads();
        if (kt + STG - 1 < T) load_stage(kt + STG - 1, (kt + STG - 1) % STG);
        else cp_async_commit();                // keep group count consistent

        const float* As = smx + (kt % STG) * (AS_SZ + BS_SZ);
        const float* Bs = As + AS_SZ;
#pragma unroll
        for (int kk = 0; kk < BK; kk += 8) {
            uint32_t a[4][4];
#pragma unroll
            for (int i = 0; i < 4; i++) {
                const int rb = wm * 64 + i * 16;
                a[i][0] = __float_as_uint(As[(rb + g) * LDT + kk + t]);
                a[i][1] = __float_as_uint(As[(rb + g + 8) * LDT + kk + t]);
                a[i][2] = __float_as_uint(As[(rb + g) * LDT + kk + t + 4]);
                a[i][3] = __float_as_uint(As[(rb + g + 8) * LDT + kk + t + 4]);
            }
            uint32_t bf[8][2];
#pragma unroll
            for (int j = 0; j < 8; j++) {
                const int nb = wn * 64 + j * 8;
                bf[j][0] = __float_as_uint(Bs[(nb + g) * LDT + kk + t]);
                bf[j][1] = __float_as_uint(Bs[(nb + g) * LDT + kk + t + 4]);
            }
#pragma unroll
            for (int i = 0; i < 4; i++)
#pragma unroll
                for (int j = 0; j < 8; j++)
                    mma_tf32(c[i][j], a[i], bf[j][0], bf[j][1]);
        }
        __syncthreads();
    }

#pragma unroll
    for (int i = 0; i < 4; i++) {
        const int gm0 = bm + wm * 64 + i * 16 + g;
        const int gm1 = gm0 + 8;
#pragma unroll
        for (int j = 0; j < 8; j++) {
            const int gn = bn + wn * 64 + j * 8 + 2 * t;
            if (gn < N) {
                float2 v0; v0.x = c[i][j][0]; v0.y = c[i][j][1];
                float2 v1; v1.x = c[i][j][2]; v1.y = c[i][j][3];
                *(float2*)&C[(size_t)gm0 * N + gn] = v0;
                *(float2*)&C[(size_t)gm1 * N + gn] = v1;
            }
        }
    }
}

// ================== fused flash attention (tf32 mma.sync) ==================
#define KS_LD 196
#define VS_LD 136
#define PS_LD 68
#define KS_SZ (64 * KS_LD)
#define VS_SZ (64 * VS_LD)
#define PS_SZ (16 * PS_LD)
#define FLASH_SMEM ((2 * KS_SZ + 2 * VS_SZ + 8 * PS_SZ) * 4)

__global__ __launch_bounds__(256, 1)
void flash_attn(const float* __restrict__ Qb, const float* __restrict__ Kb,
                const float* __restrict__ Vb, float* __restrict__ Out) {
    extern __shared__ float sm[];
    float* KsB = sm;
    float* VsB = sm + 2 * KS_SZ;
    float* PsB = sm + 2 * KS_SZ + 2 * VS_SZ;

    const int qt   = (int)(gridDim.x - 1 - blockIdx.x);  // heavy tiles first
    const int h    = blockIdx.y;
    const int bm   = qt * 128;
    const int tid  = threadIdx.x;
    const int warp = tid >> 5, lane = tid & 31;
    const int g    = lane >> 2, t = lane & 3;
    const int row0 = bm + warp * 16 + g;
    const int row1 = row0 + 8;

    const float* Qh = Qb + (size_t)h * S * QKD;
    const float* Kh = Kb + (size_t)h * S * QKD;
    const float* Vh = Vb + (size_t)h * S * DV;
    float* Pw = PsB + warp * PS_SZ;

    uint32_t qa[24][4];
    {
        const float* q0 = Qh + (size_t)row0 * QKD;
        const float* q1 = Qh + (size_t)row1 * QKD;
#pragma unroll
        for (int kg = 0; kg < 24; kg++) {
            qa[kg][0] = __float_as_uint(__ldg(q0 + 8 * kg + t));
            qa[kg][1] = __float_as_uint(__ldg(q1 + 8 * kg + t));
            qa[kg][2] = __float_as_uint(__ldg(q0 + 8 * kg + t + 4));
            qa[kg][3] = __float_as_uint(__ldg(q1 + 8 * kg + t + 4));
        }
    }

    float o[16][4];
#pragma unroll
    for (int i = 0; i < 16; i++) { o[i][0] = o[i][1] = o[i][2] = o[i][3] = 0.f; }
    float m0 = -1e30f, m1 = -1e30f, l0 = 0.f, l1 = 0.f;

    const int NT = 2 * qt + 2;

    auto load_kv = [&](int jtile, int buf) {
        const float* ksrc = Kh + (size_t)(64 * jtile) * QKD;
        float* kdst = KsB + buf * KS_SZ;
#pragma unroll
        for (int i = 0; i < 12; i++) {
            int c = tid + i * 256;
            int r = c / 48, col = (c % 48) * 4;
            cp_async16(kdst + r * KS_LD + col, ksrc + (size_t)r * QKD + col, true);
        }
        const float* vsrc = Vh + (size_t)(64 * jtile) * DV;
        float* vdst = VsB + buf * VS_SZ;
#pragma unroll
        for (int i = 0; i < 8; i++) {
            int c = tid + i * 256;
            int r = c >> 5, col = (c & 31) * 4;
            cp_async16(vdst + r * VS_LD + col, vsrc + (size_t)r * DV + col, true);
        }
    };

    load_kv(0, 0);
    cp_async_commit();

    for (int jt = 0; jt < NT; jt++) {
        const int buf = jt & 1;
        __syncthreads();
        if (jt + 1 < NT) { load_kv(jt + 1, buf ^ 1); cp_async_commit(); cp_async_wait<1>(); }
        else             { cp_async_wait<0>(); }
        __syncthreads();

        const float* Kst = KsB + buf * KS_SZ;
        const float* Vst = VsB + buf * VS_SZ;

        float sc[8][4];
#pragma unroll
        for (int njp = 0; njp < 4; njp++) {
            float s0[4] = {0.f, 0.f, 0.f, 0.f};
            float s1[4] = {0.f, 0.f, 0.f, 0.f};
            const float* kr0 = Kst + (size_t)((2 * njp) * 8 + g) * KS_LD;
            const float* kr1 = Kst + (size_t)((2 * njp + 1) * 8 + g) * KS_LD;
#pragma unroll
            for (int kg = 0; kg < 24; kg++) {
                uint32_t b0 = __float_as_uint(kr0[8 * kg + t]);
                uint32_t b1 = __float_as_uint(kr0[8 * kg + t + 4]);
                mma_tf32(s0, qa[kg], b0, b1);
                uint32_t b2 = __float_as_uint(kr1[8 * kg + t]);
                uint32_t b3 = __float_as_uint(kr1[8 * kg + t + 4]);
                mma_tf32(s1, qa[kg], b2, b3);
            }
#pragma unroll
            for (int e = 0; e < 4; e++) { sc[2 * njp][e] = s0[e]; sc[2 * njp + 1][e] = s1[e]; }
        }

#pragma unroll
        for (int nj = 0; nj < 8; nj++) {
            int colb = 64 * jt + 8 * nj + 2 * t;
            if (colb     > row0) sc[nj][0] = -1e30f;
            if (colb + 1 > row0) sc[nj][1] = -1e30f;
            if (colb     > row1) sc[nj][2] = -1e30f;
            if (colb + 1 > row1) sc[nj][3] = -1e30f;
        }

        float tm0 = -1e30f, tm1 = -1e30f;
#pragma unroll
        for (int nj = 0; nj < 8; nj++) {
            tm0 = fmaxf(tm0, fmaxf(sc[nj][0], sc[nj][1]));
            tm1 = fmaxf(tm1, fmaxf(sc[nj][2], sc[nj][3]));
        }
        tm0 = fmaxf(tm0, __shfl_xor_sync(0xffffffffu, tm0, 1));
        tm0 = fmaxf(tm0, __shfl_xor_sync(0xffffffffu, tm0, 2));
        tm1 = fmaxf(tm1, __shfl_xor_sync(0xffffffffu, tm1, 1));
        tm1 = fmaxf(tm1, __shfl_xor_sync(0xffffffffu, tm1, 2));
        const float nm0 = fmaxf(m0, tm0), nm1 = fmaxf(m1, tm1);
        const float al0 = expf((m0 - nm0) * SM_SCALE);
        const float al1 = expf((m1 - nm1) * SM_SCALE);

        float rs0 = 0.f, rs1 = 0.f;
#pragma unroll
        for (int nj = 0; nj < 8; nj++) {
            float p0 = expf((sc[nj][0] - nm0) * SM_SCALE);
            float p1 = expf((sc[nj][1] - nm0) * SM_SCALE);
            float p2 = expf((sc[nj][2] - nm1) * SM_SCALE);
            float p3 = expf((sc[nj][3] - nm1) * SM_SCALE);
            rs0 += p0 + p1;
            rs1 += p2 + p3;
            uint2 u01; u01.x = f2tf(p0); u01.y = f2tf(p1);
            uint2 u23; u23.x = f2tf(p2); u23.y = f2tf(p3);
            *(uint2*)(Pw + g * PS_LD + 8 * nj + 2 * t)       = u01;
            *(uint2*)(Pw + (g + 8) * PS_LD + 8 * nj + 2 * t) = u23;
        }
        l0 = l0 * al0 + rs0;
        l1 = l1 * al1 + rs1;
        m0 = nm0; m1 = nm1;
#pragma unroll
        for (int dj = 0; dj < 16; dj++) {
            o[dj][0] *= al0; o[dj][1] *= al0;
            o[dj][2] *= al1; o[dj][3] *= al1;
        }
        __syncwarp();

#pragma unroll
        for (int kg = 0; kg < 8; kg++) {
            uint32_t pa[4];
            pa[0] = __float_as_uint(Pw[g * PS_LD + 8 * kg + t]);
            pa[1] = __float_as_uint(Pw[(g + 8) * PS_LD + 8 * kg + t]);
            pa[2] = __float_as_uint(Pw[g * PS_LD + 8 * kg + t + 4]);
            pa[3] = __float_as_uint(Pw[(g + 8) * PS_LD + 8 * kg + t + 4]);
            const float* v0 = Vst + (size_t)(8 * kg + t) * VS_LD;
            const float* v1 = Vst + (size_t)(8 * kg + t + 4) * VS_LD;
#pragma unroll
            for (int dj = 0; dj < 16; dj += 2) {
                uint32_t b0 = __float_as_uint(v0[8 * dj + g]);
                uint32_t b1 = __float_as_uint(v1[8 * dj + g]);
                mma_tf32(o[dj], pa, b0, b1);
                uint32_t b2 = __float_as_uint(v0[8 * (dj + 1) + g]);
                uint32_t b3 = __float_as_uint(v1[8 * (dj + 1) + g]);
                mma_tf32(o[dj + 1], pa, b2, b3);
            }
        }
        __syncwarp();
    }

    // quad reduction of softmax denominator
    l0 += __shfl_xor_sync(0xffffffffu, l0, 1);
    l0 += __shfl_xor_sync(0xffffffffu, l0, 2);
    l1 += __shfl_xor_sync(0xffffffffu, l1, 1);
    l1 += __shfl_xor_sync(0xffffffffu, l1, 2);

    const float inv0 = 1.f / l0, inv1 = 1.f / l1;
    float* or0 = Out + (size_t)row0 * Hh + h * DV;
    float* or1 = Out + (size_t)row1 * Hh + h * DV;
#pragma unroll
    for (int dj = 0; dj < 16; dj++) {
        float2 w0; w0.x = tf32r(o[dj][0] * inv0); w0.y = tf32r(o[dj][1] * inv0);
        float2 w1; w1.x = tf32r(o[dj][2] * inv1); w1.y = tf32r(o[dj][3] * inv1);
        *(float2*)(or0 + 8 * dj + 2 * t) = w0;
        *(float2*)(or1 + 8 * dj + 2 * t) = w1;
    }
}

// ---------------- rmsnorm over first K cols; output tf32-rounded ----------------
__global__ void rmsnorm_kernel(const float* __restrict__ X, const float* __restrict__ w,
                               float* __restrict__ Y, int K, int ldx, int ldy) {
    const int row = blockIdx.x;
    const float* x = X + (size_t)row * ldx;
    float* y = Y + (size_t)row * ldy;
    float ss = 0.f;
    for (int j = threadIdx.x; j < K; j += blockDim.x) { float v = x[j]; ss += v * v; }
    __shared__ float red[256];
    red[threadIdx.x] = ss;
    __syncthreads();
    for (int s = 128; s > 0; s >>= 1) {
        if (threadIdx.x < s) red[threadIdx.x] += red[threadIdx.x + s];
        __syncthreads();
    }
    float inv = rsqrtf(red[0] / (float)K + 1e-6f);
    for (int j = threadIdx.x; j < K; j += blockDim.x) y[j] = tf32r(x[j] * inv * w[j]);
}

// ---------------- build Q[h][s][0..192) with RoPE; tf32-rounded ----------------
__global__ void build_q(const float* __restrict__ q, const float* __restrict__ freqs,
                        float* __restrict__ Qb) {
    const int s = blockIdx.x, h = blockIdx.y, d = threadIdx.x;
    const float* qr = q + (size_t)s * (NH * QKD) + h * QKD;
    float val;
    if (d < DN) {
        val = qr[d];
    } else {
        int u = d - DN, t = u >> 1;
        float f = freqs[s * (DR / 2) + t];
        float c = cosf(f), sn = sinf(f);
        float xr = qr[DN + 2 * t], xi = qr[DN + 2 * t + 1];
        val = (u & 1) ? (xr * sn + xi * c) : (xr * c - xi * sn);
    }
    Qb[((size_t)h * S + s) * QKD + d] = tf32r(val);
}

// ---------------- build K and V; tf32-rounded ----------------
__global__ void build_kv(const float* __restrict__ kv, const float* __restrict__ ckv,
                         const float* __restrict__ freqs,
                         float* __restrict__ Kb, float* __restrict__ Vb) {
    const int s = blockIdx.x, h = blockIdx.y, d = threadIdx.x;
    const float* kvr = kv + (size_t)s * (NH * (DN + DV)) + h * (DN + DV);
    if (d < DN) {
        Kb[((size_t)h * S + s) * QKD + d] = tf32r(kvr[d]);
    } else if (d < QKD) {
        int u = d - DN, t = u >> 1;
        float f = freqs[s * (DR / 2) + t];
        float c = cosf(f), sn = sinf(f);
        const float* kr = ckv + (size_t)s * CKVW + RKV;
        float xr = kr[2 * t], xi = kr[2 * t + 1];
        Kb[((size_t)h * S + s) * QKD + d] = tf32r((u & 1) ? (xr * sn + xi * c) : (xr * c - xi * sn));
    } else {
        int dv = d - QKD;
        Vb[((size_t)h * S + s) * DV + dv] = tf32r(kvr[DN + dv]);
    }
}

// ---------------- host ----------------
static float* sym_addr(const void* symbol) {
    void* p = nullptr;
    cudaGetSymbolAddress(&p, symbol);
    return (float*)p;
}

static void launch_round(const float* src, float* dst, size_t n) {
    int n4 = (int)(n / 4);
    round_tf32_kernel<<<(n4 + 255) / 256, 256>>>((const float4*)src, (float4*)dst, n4);
}

static void launch_gemm(const float* A, const float* B, float* C, int M, int N, int K) {
    dim3 grid((N + BN - 1) / BN, M / BM);
    gemm_nt_big<<<grid, 256, GEMM_SMEM>>>(A, B, C, M, N, K);
}

extern "C" void kernel_launch(void* const* d_in, const int* in_sizes, int n_in,
                              void* d_out, int out_size) {
    const float* hidden    = (const float*)d_in[0];
    const float* freqs     = (const float*)d_in[1];
    const float* q_a_w     = (const float*)d_in[2];
    const float* q_a_ln_w  = (const float*)d_in[3];
    const float* q_b_w     = (const float*)d_in[4];
    const float* kv_a_w    = (const float*)d_in[5];
    const float* kv_a_ln_w = (const float*)d_in[6];
    const float* kv_b_w    = (const float*)d_in[7];
    const float* o_w       = (const float*)d_in[8];
    float* out = (float*)d_out;

    float* qa   = sym_addr(g_qa);
    float* qan  = sym_addr(g_qan);
    float* q    = sym_addr(g_q);
    float* ckv  = sym_addr(g_ckv);
    float* ckvn = sym_addr(g_ckvn);
    float* kv   = sym_addr(g_kv);
    float* Qb   = sym_addr(g_Q);
    float* Kb   = sym_addr(g_K);
    float* Vb   = sym_addr(g_V);
    float* attn = sym_addr(g_attn);
    float* hid  = sym_addr(g_hid);
    float* qaw  = sym_addr(g_qaw);
    float* qbw  = sym_addr(g_qbw);
    float* kvaw = sym_addr(g_kvaw);
    float* kvbw = sym_addr(g_kvbw);
    float* ow   = sym_addr(g_ow);

    cudaFuncSetAttribute(flash_attn, cudaFuncAttributeMaxDynamicSharedMemorySize, FLASH_SMEM);
    cudaFuncSetAttribute(gemm_nt_big, cudaFuncAttributeMaxDynamicSharedMemorySize, GEMM_SMEM);

    // 0) pre-round inputs to tf32 (rna), once per call
    launch_round(hidden, hid,  (size_t)S * Hh);
    launch_round(q_a_w,  qaw,  (size_t)RQ * Hh);
    launch_round(q_b_w,  qbw,  (size_t)NH * QKD * RQ);
    launch_round(kv_a_w, kvaw, (size_t)CKVW * Hh);
    launch_round(kv_b_w, kvbw, (size_t)NH * (DN + DV) * RKV);
    launch_round(o_w,    ow,   (size_t)Hh * Hh);

    // 1) q_a = hid @ qaw^T       [2048,1536]
    launch_gemm(hid, qaw, qa, S, RQ, Hh);
    // 2) rmsnorm(q_a) -> tf32
    rmsnorm_kernel<<<S, 256>>>(qa, q_a_ln_w, qan, RQ, RQ, RQ);
    // 3) q = qan @ qbw^T         [2048,6144]
    launch_gemm(qan, qbw, q, S, NH * QKD, RQ);
    // 4) ckv = hid @ kvaw^T      [2048,576]
    launch_gemm(hid, kvaw, ckv, S, CKVW, Hh);
    // 5) rmsnorm(ckv[:, :512]) -> tf32
    rmsnorm_kernel<<<S, 256>>>(ckv, kv_a_ln_w, ckvn, RKV, CKVW, RKV);
    // 6) kv = ckvn @ kvbw^T      [2048,8192]
    launch_gemm(ckvn, kvbw, kv, S, NH * (DN + DV), RKV);
    // 7) assemble Q with RoPE (tf32)
    build_q<<<dim3(S, NH), QKD>>>(q, freqs, Qb);
    // 8) assemble K (RoPE) and V (tf32)
    build_kv<<<dim3(S, NH), QKD + DV>>>(kv, ckv, freqs, Kb, Vb);
    // 9-11) fused flash attention -> g_attn (tf32-rounded)
    flash_attn<<<dim3(S / 128, NH), 256, FLASH_SMEM>>>(Qb, Kb, Vb, attn);
    // 12) out = attn @ ow^T      [2048,4096]
    launch_gemm(attn, ow, out, S, Hh, Hh);
}

// round 10
// speedup vs baseline: 3.7060x; 1.1457x over previous
#include <cuda_runtime.h>
#include <cuda_bf16.h>
#include <math.h>
#include <cstdint>
#include <cstddef>

// ---------------- problem constants ----------------
#define S    2048
#define Hh   4096
#define NH   32
#define DN   128
#define DR   64
#define DV   128
#define QKD  192          // DN + DR
#define RQ   1536
#define RKV  512
#define CKVW 576          // RKV + DR
#define W1N  (RQ + CKVW)  // 2112: merged q_a + kv_a output width

#define SM_SCALE 0.072168783648703220563f   // 192^-0.5

// ---- big GEMM tiling ----
#define BM 128
#define BN 256
#define BK 16
#define LDT 20
#define STG 4
#define AS_SZ (BM * LDT)          // 2560 floats
#define BS_SZ (BN * LDT)          // 5120 floats
#define GEMM_SMEM (STG * (AS_SZ + BS_SZ) * 4)   // 122880 B

// ---------------- scratch (device globals; allocation-free) ----------------
__device__ float g_qackv[S * W1N];          // [q_a | ckv] merged, tf32 values
__device__ float g_qan [S * RQ];
__device__ float g_q   [S * NH * QKD];
__device__ float g_ckvn[S * RKV];
__device__ float g_kv  [S * NH * (DN+DV)];
__device__ float g_Q   [(size_t)NH * S * QKD];
__device__ float g_K   [(size_t)NH * S * QKD];
__device__ float g_V   [(size_t)NH * S * DV];
__device__ float g_attn[S * Hh];
// tf32-pre-rounded copies of inputs (weights + hidden)
__device__ float g_hid [S * Hh];
__device__ float g_w1  [(size_t)W1N * Hh];  // [q_a_w ; kv_a_w] stacked along N
__device__ float g_qbw [NH * QKD * RQ];
__device__ float g_kvbw[NH * (DN+DV) * RKV];
__device__ float g_ow  [(size_t)Hh * Hh];

// ---------------- cp.async helpers ----------------
__device__ __forceinline__ void cp_async16(void* smem, const void* gmem, bool pred) {
    unsigned int s = (unsigned int)__cvta_generic_to_shared(smem);
    int sz = pred ? 16 : 0;
    asm volatile("cp.async.cg.shared.global [%0], [%1], 16, %2;\n" :: "r"(s), "l"(gmem), "r"(sz));
}
__device__ __forceinline__ void cp_async_commit() { asm volatile("cp.async.commit_group;\n"); }
template<int N_> __device__ __forceinline__ void cp_async_wait() { asm volatile("cp.async.wait_group %0;\n" :: "n"(N_)); }

// ---------------- tf32 helpers ----------------
__device__ __forceinline__ uint32_t f2tf(float x) {
    uint32_t r; asm("cvt.rna.tf32.f32 %0, %1;" : "=r"(r) : "f"(x)); return r;
}
__device__ __forceinline__ float tf32r(float x) { return __uint_as_float(f2tf(x)); }
__device__ __forceinline__ void mma_tf32(float* c, const uint32_t* a, uint32_t b0, uint32_t b1) {
    asm("mma.sync.aligned.m16n8k8.row.col.f32.tf32.tf32.f32 "
        "{%0,%1,%2,%3},{%4,%5,%6,%7},{%8,%9},{%0,%1,%2,%3};"
        : "+f"(c[0]), "+f"(c[1]), "+f"(c[2]), "+f"(c[3])
        : "r"(a[0]), "r"(a[1]), "r"(a[2]), "r"(a[3]), "r"(b0), "r"(b1));
}

// ---------------- elementwise tf32 rounding (float4 vectorized) ----------------
__global__ void round_tf32_kernel(const float4* __restrict__ in, float4* __restrict__ out, int n4) {
    int i = blockIdx.x * blockDim.x + threadIdx.x;
    if (i < n4) {
        float4 v = in[i];
        v.x = tf32r(v.x); v.y = tf32r(v.y); v.z = tf32r(v.z); v.w = tf32r(v.w);
        out[i] = v;
    }
}

// ============ big NT GEMM: C[M,N] = A[M,K] * B[N,K]^T (raw mma, tf32-in) ============
// 128x256 block tile, BK=16, 4-stage cp.async, 8 warps in 2(M)x4(N), warp tile 64x64.
__global__ __launch_bounds__(256, 1)
void gemm_nt_big(const float* __restrict__ A, const float* __restrict__ B,
                 float* __restrict__ C, int M, int N, int K) {
    extern __shared__ float smx[];
    const int tid  = threadIdx.x;
    const int warp = tid >> 5, lane = tid & 31;
    const int g    = lane >> 2, t = lane & 3;
    const int wm   = warp >> 2, wn = warp & 3;
    const int bm   = blockIdx.y * BM, bn = blockIdx.x * BN;

    float c[4][8][4];
#pragma unroll
    for (int i = 0; i < 4; i++)
#pragma unroll
        for (int j = 0; j < 8; j++) { c[i][j][0] = c[i][j][1] = c[i][j][2] = c[i][j][3] = 0.f; }

    const int T = K / BK;

    auto load_stage = [&](int kt, int stg) {
        float* As = smx + stg * (AS_SZ + BS_SZ);
        float* Bs = As + AS_SZ;
        const int k0 = kt * BK;
#pragma unroll
        for (int u = 0; u < 2; u++) {          // A: 128x16 = 512 16B-chunks
            int f = tid + u * 256;
            int row = f >> 2, col = (f & 3) * 4;
            cp_async16(&As[row * LDT + col], A + (size_t)(bm + row) * K + k0 + col, true);
        }
#pragma unroll
        for (int u = 0; u < 4; u++) {          // B: 256x16 = 1024 chunks
            int f = tid + u * 256;
            int row = f >> 2, col = (f & 3) * 4;
            bool p = (bn + row) < N;
            cp_async16(&Bs[row * LDT + col],
                       B + (size_t)(p ? (bn + row) : 0) * K + k0 + col, p);
        }
        cp_async_commit();
    };

#pragma unroll
    for (int s = 0; s < STG - 1; s++) {
        if (s < T) load_stage(s, s); else cp_async_commit();
    }

    for (int kt = 0; kt < T; kt++) {
        cp_async_wait<STG - 2>();
        __syncthreads();
        if (kt + STG - 1 < T) load_stage(kt + STG - 1, (kt + STG - 1) % STG);
        else cp_async_commit();                // keep group count consistent

        const float* As = smx + (kt % STG) * (AS_SZ + BS_SZ);
        const float* Bs = As + AS_SZ;
#pragma unroll
        for (int kk = 0; kk < BK; kk += 8) {
            uint32_t a[4][4];
#pragma unroll
            for (int i = 0; i < 4; i++) {
                const int rb = wm * 64 + i * 16;
                a[i][0] = __float_as_uint(As[(rb + g) * LDT + kk + t]);
                a[i][1] = __float_as_uint(As[(rb + g + 8) * LDT + kk + t]);
                a[i][2] = __float_as_uint(As[(rb + g) * LDT + kk + t + 4]);
                a[i][3] = __float_as_uint(As[(rb + g + 8) * LDT + kk + t + 4]);
            }
            uint32_t bf[8][2];
#pragma unroll
            for (int j = 0; j < 8; j++) {
                const int nb = wn * 64 + j * 8;
                bf[j][0] = __float_as_uint(Bs[(nb + g) * LDT + kk + t]);
                bf[j][1] = __float_as_uint(Bs[(nb + g) * LDT + kk + t + 4]);
            }
#pragma unroll
            for (int i = 0; i < 4; i++)
#pragma unroll
                for (int j = 0; j < 8; j++)
                    mma_tf32(c[i][j], a[i], bf[j][0], bf[j][1]);
        }
        __syncthreads();
    }

#pragma unroll
    for (int i = 0; i < 4; i++) {
        const int gm0 = bm + wm * 64 + i * 16 + g;
        const int gm1 = gm0 + 8;
#pragma unroll
        for (int j = 0; j < 8; j++) {
            const int gn = bn + wn * 64 + j * 8 + 2 * t;
            if (gn < N) {
                float2 v0; v0.x = c[i][j][0]; v0.y = c[i][j][1];
                float2 v1; v1.x = c[i][j][2]; v1.y = c[i][j][3];
                *(float2*)&C[(size_t)gm0 * N + gn] = v0;
                *(float2*)&C[(size_t)gm1 * N + gn] = v1;
            }
        }
    }
}

// ================== fused flash attention (tf32 mma.sync) ==================
#define KS_LD 196
#define VS_LD 136
#define PS_LD 68
#define KS_SZ (64 * KS_LD)
#define VS_SZ (64 * VS_LD)
#define PS_SZ (16 * PS_LD)
#define FLASH_SMEM ((2 * KS_SZ + 2 * VS_SZ + 8 * PS_SZ) * 4)

__global__ __launch_bounds__(256, 1)
void flash_attn(const float* __restrict__ Qb, const float* __restrict__ Kb,
                const float* __restrict__ Vb, float* __restrict__ Out) {
    extern __shared__ float sm[];
    float* KsB = sm;
    float* VsB = sm + 2 * KS_SZ;
    float* PsB = sm + 2 * KS_SZ + 2 * VS_SZ;

    const int qt   = (int)(gridDim.x - 1 - blockIdx.x);  // heavy tiles first
    const int h    = blockIdx.y;
    const int bm   = qt * 128;
    const int tid  = threadIdx.x;
    const int warp = tid >> 5, lane = tid & 31;
    const int g    = lane >> 2, t = lane & 3;
    const int row0 = bm + warp * 16 + g;
    const int row1 = row0 + 8;

    const float* Qh = Qb + (size_t)h * S * QKD;
    const float* Kh = Kb + (size_t)h * S * QKD;
    const float* Vh = Vb + (size_t)h * S * DV;
    float* Pw = PsB + warp * PS_SZ;

    uint32_t qa[24][4];
    {
        const float* q0 = Qh + (size_t)row0 * QKD;
        const float* q1 = Qh + (size_t)row1 * QKD;
#pragma unroll
        for (int kg = 0; kg < 24; kg++) {
            qa[kg][0] = __float_as_uint(__ldg(q0 + 8 * kg + t));
            qa[kg][1] = __float_as_uint(__ldg(q1 + 8 * kg + t));
            qa[kg][2] = __float_as_uint(__ldg(q0 + 8 * kg + t + 4));
            qa[kg][3] = __float_as_uint(__ldg(q1 + 8 * kg + t + 4));
        }
    }

    float o[16][4];
#pragma unroll
    for (int i = 0; i < 16; i++) { o[i][0] = o[i][1] = o[i][2] = o[i][3] = 0.f; }
    float m0 = -1e30f, m1 = -1e30f, l0 = 0.f, l1 = 0.f;

    const int NT = 2 * qt + 2;

    auto load_kv = [&](int jtile, int buf) {
        const float* ksrc = Kh + (size_t)(64 * jtile) * QKD;
        float* kdst = KsB + buf * KS_SZ;
#pragma unroll
        for (int i = 0; i < 12; i++) {
            int c = tid + i * 256;
            int r = c / 48, col = (c % 48) * 4;
            cp_async16(kdst + r * KS_LD + col, ksrc + (size_t)r * QKD + col, true);
        }
        const float* vsrc = Vh + (size_t)(64 * jtile) * DV;
        float* vdst = VsB + buf * VS_SZ;
#pragma unroll
        for (int i = 0; i < 8; i++) {
            int c = tid + i * 256;
            int r = c >> 5, col = (c & 31) * 4;
            cp_async16(vdst + r * VS_LD + col, vsrc + (size_t)r * DV + col, true);
        }
    };

    load_kv(0, 0);
    cp_async_commit();

    for (int jt = 0; jt < NT; jt++) {
        const int buf = jt & 1;
        __syncthreads();
        if (jt + 1 < NT) { load_kv(jt + 1, buf ^ 1); cp_async_commit(); cp_async_wait<1>(); }
        else             { cp_async_wait<0>(); }
        __syncthreads();

        const float* Kst = KsB + buf * KS_SZ;
        const float* Vst = VsB + buf * VS_SZ;

        float sc[8][4];
#pragma unroll
        for (int njp = 0; njp < 4; njp++) {
            float s0[4] = {0.f, 0.f, 0.f, 0.f};
            float s1[4] = {0.f, 0.f, 0.f, 0.f};
            const float* kr0 = Kst + (size_t)((2 * njp) * 8 + g) * KS_LD;
            const float* kr1 = Kst + (size_t)((2 * njp + 1) * 8 + g) * KS_LD;
#pragma unroll
            for (int kg = 0; kg < 24; kg++) {
                uint32_t b0 = __float_as_uint(kr0[8 * kg + t]);
                uint32_t b1 = __float_as_uint(kr0[8 * kg + t + 4]);
                mma_tf32(s0, qa[kg], b0, b1);
                uint32_t b2 = __float_as_uint(kr1[8 * kg + t]);
                uint32_t b3 = __float_as_uint(kr1[8 * kg + t + 4]);
                mma_tf32(s1, qa[kg], b2, b3);
            }
#pragma unroll
            for (int e = 0; e < 4; e++) { sc[2 * njp][e] = s0[e]; sc[2 * njp + 1][e] = s1[e]; }
        }

#pragma unroll
        for (int nj = 0; nj < 8; nj++) {
            int colb = 64 * jt + 8 * nj + 2 * t;
            if (colb     > row0) sc[nj][0] = -1e30f;
            if (colb + 1 > row0) sc[nj][1] = -1e30f;
            if (colb     > row1) sc[nj][2] = -1e30f;
            if (colb + 1 > row1) sc[nj][3] = -1e30f;
        }

        float tm0 = -1e30f, tm1 = -1e30f;
#pragma unroll
        for (int nj = 0; nj < 8; nj++) {
            tm0 = fmaxf(tm0, fmaxf(sc[nj][0], sc[nj][1]));
            tm1 = fmaxf(tm1, fmaxf(sc[nj][2], sc[nj][3]));
        }
        tm0 = fmaxf(tm0, __shfl_xor_sync(0xffffffffu, tm0, 1));
        tm0 = fmaxf(tm0, __shfl_xor_sync(0xffffffffu, tm0, 2));
        tm1 = fmaxf(tm1, __shfl_xor_sync(0xffffffffu, tm1, 1));
        tm1 = fmaxf(tm1, __shfl_xor_sync(0xffffffffu, tm1, 2));
        const float nm0 = fmaxf(m0, tm0), nm1 = fmaxf(m1, tm1);
        const float al0 = expf((m0 - nm0) * SM_SCALE);
        const float al1 = expf((m1 - nm1) * SM_SCALE);

        float rs0 = 0.f, rs1 = 0.f;
#pragma unroll
        for (int nj = 0; nj < 8; nj++) {
            float p0 = expf((sc[nj][0] - nm0) * SM_SCALE);
            float p1 = expf((sc[nj][1] - nm0) * SM_SCALE);
            float p2 = expf((sc[nj][2] - nm1) * SM_SCALE);
            float p3 = expf((sc[nj][3] - nm1) * SM_SCALE);
            rs0 += p0 + p1;
            rs1 += p2 + p3;
            uint2 u01; u01.x = f2tf(p0); u01.y = f2tf(p1);
            uint2 u23; u23.x = f2tf(p2); u23.y = f2tf(p3);
            *(uint2*)(Pw + g * PS_LD + 8 * nj + 2 * t)       = u01;
            *(uint2*)(Pw + (g + 8) * PS_LD + 8 * nj + 2 * t) = u23;
        }
        l0 = l0 * al0 + rs0;
        l1 = l1 * al1 + rs1;
        m0 = nm0; m1 = nm1;
#pragma unroll
        for (int dj = 0; dj < 16; dj++) {
            o[dj][0] *= al0; o[dj][1] *= al0;
            o[dj][2] *= al1; o[dj][3] *= al1;
        }
        __syncwarp();

#pragma unroll
        for (int kg = 0; kg < 8; kg++) {
            uint32_t pa[4];
            pa[0] = __float_as_uint(Pw[g * PS_LD + 8 * kg + t]);
            pa[1] = __float_as_uint(Pw[(g + 8) * PS_LD + 8 * kg + t]);
            pa[2] = __float_as_uint(Pw[g * PS_LD + 8 * kg + t + 4]);
            pa[3] = __float_as_uint(Pw[(g + 8) * PS_LD + 8 * kg + t + 4]);
            const float* v0 = Vst + (size_t)(8 * kg + t) * VS_LD;
            const float* v1 = Vst + (size_t)(8 * kg + t + 4) * VS_LD;
#pragma unroll
            for (int dj = 0; dj < 16; dj += 2) {
                uint32_t b0 = __float_as_uint(v0[8 * dj + g]);
                uint32_t b1 = __float_as_uint(v1[8 * dj + g]);
                mma_tf32(o[dj], pa, b0, b1);
                uint32_t b2 = __float_as_uint(v0[8 * (dj + 1) + g]);
                uint32_t b3 = __float_as_uint(v1[8 * (dj + 1) + g]);
                mma_tf32(o[dj + 1], pa, b2, b3);
            }
        }
        __syncwarp();
    }

    // quad reduction of softmax denominator
    l0 += __shfl_xor_sync(0xffffffffu, l0, 1);
    l0 += __shfl_xor_sync(0xffffffffu, l0, 2);
    l1 += __shfl_xor_sync(0xffffffffu, l1, 1);
    l1 += __shfl_xor_sync(0xffffffffu, l1, 2);

    const float inv0 = 1.f / l0, inv1 = 1.f / l1;
    float* or0 = Out + (size_t)row0 * Hh + h * DV;
    float* or1 = Out + (size_t)row1 * Hh + h * DV;
#pragma unroll
    for (int dj = 0; dj < 16; dj++) {
        float2 w0; w0.x = tf32r(o[dj][0] * inv0); w0.y = tf32r(o[dj][1] * inv0);
        float2 w1; w1.x = tf32r(o[dj][2] * inv1); w1.y = tf32r(o[dj][3] * inv1);
        *(float2*)(or0 + 8 * dj + 2 * t) = w0;
        *(float2*)(or1 + 8 * dj + 2 * t) = w1;
    }
}

// ---------------- rmsnorm over first K cols; output tf32-rounded ----------------
__global__ void rmsnorm_kernel(const float* __restrict__ X, const float* __restrict__ w,
                               float* __restrict__ Y, int K, int ldx, int ldy) {
    const int row = blockIdx.x;
    const float* x = X + (size_t)row * ldx;
    float* y = Y + (size_t)row * ldy;
    float ss = 0.f;
    for (int j = threadIdx.x; j < K; j += blockDim.x) { float v = x[j]; ss += v * v; }
    __shared__ float red[256];
    red[threadIdx.x] = ss;
    __syncthreads();
    for (int s = 128; s > 0; s >>= 1) {
        if (threadIdx.x < s) red[threadIdx.x] += red[threadIdx.x + s];
        __syncthreads();
    }
    float inv = rsqrtf(red[0] / (float)K + 1e-6f);
    for (int j = threadIdx.x; j < K; j += blockDim.x) y[j] = tf32r(x[j] * inv * w[j]);
}

// ---------------- build Q: grid S, 256 threads; cos/sin computed once ----------------
__global__ void build_q2(const float* __restrict__ q, const float* __restrict__ freqs,
                         float* __restrict__ Qb) {
    const int s = blockIdx.x;
    __shared__ float cs[DR];          // [cos(0..31) | sin(0..31)]
    if (threadIdx.x < DR / 2) {
        float f = freqs[s * (DR / 2) + threadIdx.x];
        cs[threadIdx.x]      = cosf(f);
        cs[32 + threadIdx.x] = sinf(f);
    }
    __syncthreads();
    const float* qs = q + (size_t)s * (NH * QKD);
    for (int idx = threadIdx.x; idx < NH * QKD; idx += 256) {
        int h = idx / QKD, d = idx - h * QKD;
        float val;
        if (d < DN) {
            val = qs[h * QKD + d];
        } else {
            int u = d - DN, t = u >> 1;
            float c = cs[t], sn = cs[32 + t];
            float xr = qs[h * QKD + DN + 2 * t], xi = qs[h * QKD + DN + 2 * t + 1];
            val = (u & 1) ? (xr * sn + xi * c) : (xr * c - xi * sn);
        }
        Qb[((size_t)h * S + s) * QKD + d] = tf32r(val);
    }
}

// ---------------- build K/V: rot part computed once (shared across heads) ----------------
__global__ void build_kv2(const float* __restrict__ kv, const float* __restrict__ qackv,
                          const float* __restrict__ freqs,
                          float* __restrict__ Kb, float* __restrict__ Vb) {
    const int s = blockIdx.x;
    __shared__ float rot[DR];
    if (threadIdx.x < DR / 2) {
        float f = freqs[s * (DR / 2) + threadIdx.x];
        float c = cosf(f), sn = sinf(f);
        const float* kr = qackv + (size_t)s * W1N + (RQ + RKV);
        float xr = kr[2 * threadIdx.x], xi = kr[2 * threadIdx.x + 1];
        rot[2 * threadIdx.x]     = tf32r(xr * c - xi * sn);
        rot[2 * threadIdx.x + 1] = tf32r(xr * sn + xi * c);
    }
    __syncthreads();
    const float* kvs = kv + (size_t)s * (NH * (DN + DV));
    const int PER = DN + DV + DR;    // 320 outputs per head
    for (int idx = threadIdx.x; idx < NH * PER; idx += 256) {
        int h = idx / PER, d = idx - h * PER;
        if (d < DN) {
            Kb[((size_t)h * S + s) * QKD + d] = tf32r(kvs[h * (DN + DV) + d]);
        } else if (d < QKD) {
            Kb[((size_t)h * S + s) * QKD + d] = rot[d - DN];
        } else {
            int dv = d - QKD;
            Vb[((size_t)h * S + s) * DV + dv] = tf32r(kvs[h * (DN + DV) + DN + dv]);
        }
    }
}

// ---------------- host ----------------
static float* sym_addr(const void* symbol) {
    void* p = nullptr;
    cudaGetSymbolAddress(&p, symbol);
    return (float*)p;
}

static void launch_round(const float* src, float* dst, size_t n) {
    int n4 = (int)(n / 4);
    round_tf32_kernel<<<(n4 + 255) / 256, 256>>>((const float4*)src, (float4*)dst, n4);
}

static void launch_gemm(const float* A, const float* B, float* C, int M, int N, int K) {
    dim3 grid((N + BN - 1) / BN, M / BM);
    gemm_nt_big<<<grid, 256, GEMM_SMEM>>>(A, B, C, M, N, K);
}

extern "C" void kernel_launch(void* const* d_in, const int* in_sizes, int n_in,
                              void* d_out, int out_size) {
    const float* hidden    = (const float*)d_in[0];
    const float* freqs     = (const float*)d_in[1];
    const float* q_a_w     = (const float*)d_in[2];
    const float* q_a_ln_w  = (const float*)d_in[3];
    const float* q_b_w     = (const float*)d_in[4];
    const float* kv_a_w    = (const float*)d_in[5];
    const float* kv_a_ln_w = (const float*)d_in[6];
    const float* kv_b_w    = (const float*)d_in[7];
    const float* o_w       = (const float*)d_in[8];
    float* out = (float*)d_out;

    float* qackv = sym_addr(g_qackv);
    float* qan  = sym_addr(g_qan);
    float* q    = sym_addr(g_q);
    float* ckvn = sym_addr(g_ckvn);
    float* kv   = sym_addr(g_kv);
    float* Qb   = sym_addr(g_Q);
    float* Kb   = sym_addr(g_K);
    float* Vb   = sym_addr(g_V);
    float* attn = sym_addr(g_attn);
    float* hid  = sym_addr(g_hid);
    float* w1   = sym_addr(g_w1);
    float* qbw  = sym_addr(g_qbw);
    float* kvbw = sym_addr(g_kvbw);
    float* ow   = sym_addr(g_ow);

    cudaFuncSetAttribute(flash_attn, cudaFuncAttributeMaxDynamicSharedMemorySize, FLASH_SMEM);
    cudaFuncSetAttribute(gemm_nt_big, cudaFuncAttributeMaxDynamicSharedMemorySize, GEMM_SMEM);

    // 0) pre-round inputs to tf32 (rna), once per call
    launch_round(hidden, hid,  (size_t)S * Hh);
    launch_round(q_a_w,  w1,                    (size_t)RQ * Hh);    // rows 0..1535
    launch_round(kv_a_w, w1 + (size_t)RQ * Hh,  (size_t)CKVW * Hh);  // rows 1536..2111
    launch_round(q_b_w,  qbw,  (size_t)NH * QKD * RQ);
    launch_round(kv_b_w, kvbw, (size_t)NH * (DN + DV) * RKV);
    launch_round(o_w,    ow,   (size_t)Hh * Hh);

    // 1) [q_a | ckv] = hid @ w1^T   [2048, 2112]  (merged G1+G4, one full wave)
    launch_gemm(hid, w1, qackv, S, W1N, Hh);
    // 2) rmsnorm(q_a) -> tf32
    rmsnorm_kernel<<<S, 256>>>(qackv, q_a_ln_w, qan, RQ, W1N, RQ);
    // 3) q = qan @ qbw^T            [2048,6144]
    launch_gemm(qan, qbw, q, S, NH * QKD, RQ);
    // 5) rmsnorm(ckv[:, :512]) -> tf32
    rmsnorm_kernel<<<S, 256>>>(qackv + RQ, kv_a_ln_w, ckvn, RKV, W1N, RKV);
    // 6) kv = ckvn @ kvbw^T         [2048,8192]
    launch_gemm(ckvn, kvbw, kv, S, NH * (DN + DV), RKV);
    // 7) assemble Q with RoPE (tf32)
    build_q2<<<S, 256>>>(q, freqs, Qb);
    // 8) assemble K (RoPE, shared rot) and V (tf32)
    build_kv2<<<S, 256>>>(kv, qackv, freqs, Kb, Vb);
    // 9-11) fused flash attention -> g_attn (tf32-rounded)
    flash_attn<<<dim3(S / 128, NH), 256, FLASH_SMEM>>>(Qb, Kb, Vb, attn);
    // 12) out = attn @ ow^T         [2048,4096]
    launch_gemm(attn, ow, out, S, Hh, Hh);
}